// round 13
// baseline (speedup 1.0000x reference)
#include <cuda_runtime.h>
#include <cuda_fp16.h>
#include <math.h>
#include <stdint.h>

#define Bb 32
#define Ss 512
#define Hh 256
#define BS (Bb*Ss)          // 16384 rows
#define NG 1792             // 7 gates * 256 (biasmat width)
#define NG2 2048            // GEMM N: 7 gates + fgi projection
#define CHK 16              // K chunks (64 cols) : K = 1024, fp16 hi only
#define ABLK (128*128)      // A chunk block bytes = 16KB
#define BBLK (128*128)      // B chunk block bytes = 16KB
#define NSTG 3
#define STG (ABLK + BBLK)   // 32KB
#define SMEM_MMA (1024 + NSTG*STG + 64)
#define NTILE 2048          // 16 (n) x 128 (m)
#define NCTA 296

// ---------------- scratch (device globals; no allocation allowed) ----------------
__device__ float g_hh[2][BS*Hh];
__device__ float g_cs[2][BS*Hh];
__device__ float g_sv[2][Bb*Hh];
__device__ float g_scs[2][Bb*Hh];
__device__ float g_fgsm[Bb*Hh];
__device__ float g_ogg[Bb*Hh];
__device__ float g_svproj[Bb*Hh];
__device__ float g_biasmat[Bb*NG];
__device__ __half g_preh[(size_t)BS*NG2];     // fp16 pre-activations (67MB)
__device__ float g_sc[BS*Hh];
__device__ float g_Wgt[Hh*NG];                // W_g transposed  [k][g*256+h]
__device__ float g_WsmT[5][Hh*Hh];            // transposed small gates
__device__ float g_W1t[512*Hh];               // W1^T [k][h]
// A: [128 mtiles][16 chunks][128 rows][64 cols] fp16 hi, pre-swizzled (32MB)
__device__ __align__(256) __half g_Xs[(size_t)128*16*128*64];
// B: [16 ntiles][16 chunks][128 rows][64 cols] fp16 hi, pre-swizzled (4MB, L2-resident)
__device__ __align__(256) __half g_Wn[(size_t)16*16*128*64];

__device__ __forceinline__ float sigmoidf(float x){ return 1.f/(1.f+expf(-x)); }

__device__ __forceinline__ uint32_t smem_u32(const void* p){
    uint32_t a;
    asm("{ .reg .u64 t; cvta.to.shared.u64 t, %1; cvt.u32.u64 %0, t; }" : "=r"(a) : "l"(p));
    return a;
}

__device__ __forceinline__ void ldsm4(uint32_t (&r)[4], uint32_t a){
    asm volatile("ldmatrix.sync.aligned.m8n8.x4.shared.b16 {%0,%1,%2,%3}, [%4];"
        : "=r"(r[0]), "=r"(r[1]), "=r"(r[2]), "=r"(r[3]) : "r"(a));
}

__device__ __forceinline__ void mma16816(float (&c)[4], const uint32_t (&a)[4],
                                         uint32_t b0, uint32_t b1){
    asm volatile("mma.sync.aligned.m16n8k16.row.col.f32.f16.f16.f32 "
        "{%0,%1,%2,%3}, {%4,%5,%6,%7}, {%8,%9}, {%0,%1,%2,%3};"
        : "+f"(c[0]), "+f"(c[1]), "+f"(c[2]), "+f"(c[3])
        : "r"(a[0]), "r"(a[1]), "r"(a[2]), "r"(a[3]), "r"(b0), "r"(b1));
}

__device__ __forceinline__ void mbar_wait(uint32_t mbar, uint32_t parity){
    uint32_t done;
    asm volatile("{\n\t.reg .pred p;\n\tmbarrier.try_wait.parity.acquire.cta.shared::cta.b64 p, [%1], %2;\n\tselp.b32 %0, 1, 0, p;\n\t}"
        : "=r"(done) : "r"(mbar), "r"(parity) : "memory");
    while (!done){
        asm volatile("{\n\t.reg .pred p;\n\tmbarrier.try_wait.parity.acquire.cta.shared::cta.b64 p, [%1], %2, 0x989680;\n\tselp.b32 %0, 1, 0, p;\n\t}"
            : "=r"(done) : "r"(mbar), "r"(parity) : "memory");
    }
}

__device__ __forceinline__ float warp_sum(float v){
    #pragma unroll
    for (int o = 16; o > 0; o >>= 1) v += __shfl_xor_sync(0xffffffffu, v, o);
    return v;
}

__device__ __forceinline__ void store_seg8(int mtile, int r, int col0, const float* v){
    // store 8 fp16 at logical column col0 (multiple of 8) of row (mtile,r), swizzled
    __align__(16) __half o[8];
    #pragma unroll
    for (int j = 0; j < 8; j++) o[j] = __float2half_rn(v[j]);
    int chunk = col0 >> 6, within = col0 & 63;
    uint32_t cb = ((uint32_t)within*2) ^ ((uint32_t)(r & 7) << 4);
    char* dst = (char*)g_Xs + ((size_t)(mtile*CHK + chunk))*ABLK + (size_t)r*128 + cb;
    *(uint4*)dst = *(const uint4*)o;
}

// ---------------- setup kernels ----------------
// W rows -> fp16, chunked pre-swizzled; n in [1792,2048) = fgi projection columns
__global__ void k_wsplit(const float* __restrict__ W_lr, const float* __restrict__ W_c,
                         const float* __restrict__ W_x, const float* __restrict__ W_fgi_h){
    int n = blockIdx.x;            // 0..2047
    int ntile = n >> 7, r = n & 127;
    int k0 = threadIdx.x * 8;      // 128 threads
    float4 a = make_float4(0.f,0.f,0.f,0.f), b = a;
    if (n < NG){
        int g = n >> 8, h = n & 255;
        const float* src;
        if (k0 < 512)      src = W_lr + ((size_t)g*Hh + h)*512 + k0;
        else if (k0 < 768) src = W_c  + ((size_t)g*Hh + h)*Hh + (k0-512);
        else               src = W_x  + ((size_t)g*Hh + h)*Hh + (k0-768);
        a = *(const float4*)src;
        b = *(const float4*)(src + 4);
    } else if (k0 >= 512 && k0 < 768){
        int h = n - NG;
        const float* src = W_fgi_h + (size_t)h*Hh + (k0-512);
        a = *(const float4*)src;
        b = *(const float4*)(src + 4);
    }
    __align__(16) __half o[8];
    o[0]=__float2half_rn(a.x); o[1]=__float2half_rn(a.y);
    o[2]=__float2half_rn(a.z); o[3]=__float2half_rn(a.w);
    o[4]=__float2half_rn(b.x); o[5]=__float2half_rn(b.y);
    o[6]=__float2half_rn(b.z); o[7]=__float2half_rn(b.w);
    int chunk = k0 >> 6, within = k0 & 63;
    uint32_t cb = ((uint32_t)within*2) ^ ((uint32_t)(r & 7) << 4);
    char* dst = (char*)g_Wn + ((size_t)(ntile*CHK + chunk))*BBLK + (size_t)r*128 + cb;
    *(uint4*)dst = *(const uint4*)o;
}

__global__ void k_wgt(const float* __restrict__ W_g){
    int k = blockIdx.x, g = blockIdx.y, h = threadIdx.x;
    g_Wgt[(size_t)k*NG + g*Hh + h] = W_g[((size_t)(g*Hh+h))*Hh + k];
}

__global__ void k_wsmt(const float* __restrict__ W_fg_g, const float* __restrict__ W_fg_h,
                       const float* __restrict__ W_og_g, const float* __restrict__ W_og_h,
                       const float* __restrict__ W_fgi_g){
    int k = blockIdx.x, which = blockIdx.y, h = threadIdx.x;
    const float* src = (which == 0) ? W_fg_g : (which == 1) ? W_fg_h :
                       (which == 2) ? W_og_g : (which == 3) ? W_og_h : W_fgi_g;
    g_WsmT[which][k*Hh + h] = src[(size_t)h*Hh + k];
}

__global__ void k_w1t(const float* __restrict__ W1){
    int k = blockIdx.x, h = threadIdx.x;
    g_W1t[k*Hh + h] = W1[(size_t)h*512 + k];
}

// wv segment (cols 768..1023) of Xs — layer-invariant, filled once
__global__ void __launch_bounds__(1024) k_wvseg(const int* __restrict__ idx,
                                                const float* __restrict__ embed){
    int t = threadIdx.x;
    int m = blockIdx.x*32 + (t >> 5);
    int mtile = m >> 7, r = m & 127;
    int h0 = (t & 31) * 8;
    const float* src = embed + (size_t)idx[m]*Hh + h0;
    float4 a = *(const float4*)src, b = *(const float4*)(src + 4);
    float v[8] = {a.x,a.y,a.z,a.w,b.x,b.y,b.z,b.w};
    store_seg8(mtile, r, 768 + h0, v);
}

// hh segment (cols 512..767) of Xs from a full-precision hh source (layer-0 setup)
__global__ void __launch_bounds__(1024) k_hhseg(const float* __restrict__ hh_p){
    int t = threadIdx.x;
    int m = blockIdx.x*32 + (t >> 5);
    int mtile = m >> 7, r = m & 127;
    int h0 = (t & 31) * 8;
    const float* src = hh_p + (size_t)m*Hh + h0;
    float4 a = *(const float4*)src, b = *(const float4*)(src + 4);
    float v[8] = {a.x,a.y,a.z,a.w,b.x,b.y,b.z,b.w};
    store_seg8(mtile, r, 512 + h0, v);
}

// ---------------- per-layer kernels ----------------
// hb|ha segments (cols 0..511) of Xs; 16 rows per 1024-thr block
__global__ void __launch_bounds__(1024) k_buildXs01(const float* hh_ext){
    const float* hh = hh_ext ? hh_ext : g_hh[0];
    int t = threadIdx.x;
    int m = blockIdx.x*16 + (t >> 6);
    int mtile = m >> 7, r = m & 127, s = m % Ss;
    int sc0 = (t & 63) * 8;               // 0..504
    int seg = sc0 >> 8, h0 = sc0 & 255;
    float v[8];
    #pragma unroll
    for (int j = 0; j < 8; j++) v[j] = 0.f;
    auto add8 = [&](const float* pp){
        float4 a = *(const float4*)pp;
        float4 b = *(const float4*)(pp + 4);
        v[0]+=a.x; v[1]+=a.y; v[2]+=a.z; v[3]+=a.w;
        v[4]+=b.x; v[5]+=b.y; v[6]+=b.z; v[7]+=b.w;
    };
    if (seg == 0){
        if (s >= 1) add8(hh + (size_t)(m-1)*Hh + h0);
        if (s >= 2) add8(hh + (size_t)(m-2)*Hh + h0);
    } else {
        if (s+1 < Ss) add8(hh + (size_t)(m+1)*Hh + h0);
        if (s+2 < Ss) add8(hh + (size_t)(m+2)*Hh + h0);
    }
    store_seg8(mtile, r, sc0, v);
}

// small sentence gates; layer0: compute avgs from external hh0/cs0 and init scs
__global__ void __launch_bounds__(1024) k_small(const float* __restrict__ b_fg,
                        const float* __restrict__ gate_bias,
                        const float* hh_ext, const float* cs_ext, int l){
    __shared__ float ssv[Hh], sav[Hh];
    __shared__ float pf[4][Hh], po[4][Hh], psp[4][Hh];
    __shared__ float red[32];
    int b = blockIdx.x, t = threadIdx.x, h = t & 255, qd = t >> 8;
    const float* hh_p = hh_ext ? hh_ext : g_hh[0];
    float av = 0.f;
    for (int s2 = 0; s2 < 128; s2++) av += hh_p[(size_t)(b*Ss + qd*128 + s2)*Hh + h];
    pf[qd][h] = av;
    if (l == 0){
        float cv = 0.f;
        for (int s2 = 0; s2 < 128; s2++) cv += cs_ext[(size_t)(b*Ss + qd*128 + s2)*Hh + h];
        po[qd][h] = cv;
    } else {
        if (t < 256) ssv[h] = g_sv[1][b*Hh+h];
    }
    __syncthreads();
    if (t < 256){
        sav[h] = (pf[0][h]+pf[1][h]+pf[2][h]+pf[3][h]) * (1.f/Ss);
        if (l == 0){
            g_scs[0][b*Hh+h] = (po[0][h]+po[1][h]+po[2][h]+po[3][h]) * (1.f/Ss);
            ssv[h] = sav[h];
        }
    }
    __syncthreads();
    float f = 0.f, o = 0.f, sp = 0.f;
    int k0 = qd*64;
    #pragma unroll 4
    for (int k = k0; k < k0+64; k++){
        float s = ssv[k], a = sav[k];
        int off = k*Hh + h;
        f  += s*g_WsmT[0][off] + a*g_WsmT[1][off];
        o  += s*g_WsmT[2][off] + a*g_WsmT[3][off];
        sp += s*g_WsmT[4][off];
    }
    pf[qd][h] = f; po[qd][h] = o; psp[qd][h] = sp;
    __syncthreads();
    float e = 0.f;
    if (t < 256){
        f  = pf[0][h]+pf[1][h]+pf[2][h]+pf[3][h] + b_fg[h];
        o  = po[0][h]+po[1][h]+po[2][h]+po[3][h] + gate_bias[5*Hh + h];
        sp = psp[0][h]+psp[1][h]+psp[2][h]+psp[3][h];
        f = sigmoidf(f);
        g_ogg[b*Hh+h]    = sigmoidf(o);
        g_svproj[b*Hh+h] = sp;
        e = expf(f);
    }
    int lane = t & 31, w = t >> 5;
    float r = warp_sum(e);
    if (lane == 0) red[w] = r;
    __syncthreads();
    if (t < 32){
        float rr = red[t];
        #pragma unroll
        for (int o2 = 16; o2 > 0; o2 >>= 1) rr += __shfl_xor_sync(0xffffffffu, rr, o2);
        if (t == 0) red[0] = rr;
    }
    __syncthreads();
    if (t < 256) g_fgsm[b*Hh+h] = e / red[0];
}

// fgi softmax, warp-per-row (8 rows/block), shuffle-only reduce
__global__ void __launch_bounds__(256) k_fgi(const float* __restrict__ b_fgi,
                                             const float* cs_ext){
    const float* cs_p = cs_ext ? cs_ext : g_cs[0];
    int t = threadIdx.x, wid = t >> 5, lane = t & 31;
    int m = blockIdx.x*8 + wid;
    int b = m / Ss;
    int h0 = lane*8;
    __align__(16) __half hbuf[8];
    *(uint4*)hbuf = *(const uint4*)(g_preh + (size_t)m*NG2 + NG + h0);
    float4 s0 = *(const float4*)(g_svproj + b*Hh + h0);
    float4 s1 = *(const float4*)(g_svproj + b*Hh + h0 + 4);
    float4 f0 = *(const float4*)(b_fgi + h0);
    float4 f1 = *(const float4*)(b_fgi + h0 + 4);
    float sp[8] = {s0.x,s0.y,s0.z,s0.w,s1.x,s1.y,s1.z,s1.w};
    float bf[8] = {f0.x,f0.y,f0.z,f0.w,f1.x,f1.y,f1.z,f1.w};
    float e[8]; float esum = 0.f;
    #pragma unroll
    for (int j = 0; j < 8; j++){
        float x = __half2float(hbuf[j]) + sp[j] + bf[j];
        e[j] = __expf(__fdividef(1.f, 1.f + __expf(-x)));
        esum += e[j];
    }
    float inv = __fdividef(1.f, warp_sum(esum));
    const float* csr = cs_p + (size_t)m*Hh + h0;
    float4 c0 = *(const float4*)csr;
    float4 c1 = *(const float4*)(csr + 4);
    float cv[8] = {c0.x,c0.y,c0.z,c0.w,c1.x,c1.y,c1.z,c1.w};
    float4 o0, o1;
    o0.x = e[0]*inv*cv[0]; o0.y = e[1]*inv*cv[1]; o0.z = e[2]*inv*cv[2]; o0.w = e[3]*inv*cv[3];
    o1.x = e[4]*inv*cv[4]; o1.y = e[5]*inv*cv[5]; o1.z = e[6]*inv*cv[6]; o1.w = e[7]*inv*cv[7];
    float* dst = g_sc + (size_t)m*Hh + h0;
    *(float4*)dst = o0;
    *(float4*)(dst + 4) = o1;
}

// merged: new_scs/new_sv + biasmat; layer index l: p=g_scs[l], q=1-l
__global__ void __launch_bounds__(1024) k_scsbias(const float* __restrict__ gate_bias, int l){
    __shared__ float ps[4][Hh];
    __shared__ float ssv[Hh];
    __shared__ float pa[4][Hh];
    int b = blockIdx.x, t = threadIdx.x, h = t & 255, qd = t >> 8;
    float acc = 0.f;
    for (int s2 = 0; s2 < 128; s2++) acc += g_sc[(size_t)(b*Ss + qd*128 + s2)*Hh + h];
    ps[qd][h] = acc;
    __syncthreads();
    if (t < 256){
        int i = b*Hh + h;
        float ns = g_fgsm[i]*g_scs[l][i] + ps[0][h]+ps[1][h]+ps[2][h]+ps[3][h];
        g_scs[1-l][i] = ns;
        float nsv = g_ogg[i] * tanhf(ns);
        g_sv[1-l][i] = nsv;
        ssv[h] = nsv;
    }
    __syncthreads();
    #pragma unroll
    for (int g = 0; g < 7; g++){
        float a = 0.f;
        int k0 = qd*64;
        #pragma unroll 4
        for (int k = k0; k < k0+64; k++)
            a += ssv[k] * g_Wgt[(size_t)k*NG + g*Hh + h];
        pa[qd][h] = a;
        __syncthreads();
        if (t < 256)
            g_biasmat[(size_t)b*NG + g*Hh + h] = gate_bias[g*Hh+h] + pa[0][h]+pa[1][h]+pa[2][h]+pa[3][h];
        __syncthreads();
    }
}

// ---------------- bulk-copy HMMA GEMM: preh = X @ Wn^T ----------------
// persistent, tile 128x128, 4 warps of 64x64, 3-stage bulk+mbarrier, 2 CTAs/SM,
// fragment double-buffering across ks + early empty-arrive after last LDSM
__global__ void __launch_bounds__(128,2) k_mma(int cap){
    extern __shared__ char smc[];
    uint32_t sb = smem_u32(smc);
    uint32_t dbase = (sb + 1023) & ~1023u;
    uint32_t mb = dbase + NSTG*STG;
    int tid = threadIdx.x, wid = tid >> 5, lane = tid & 31;
    int wm = wid >> 1, wn = wid & 1;     // warp tile 64(M) x 64(N)

    if (tid == 0){
        #pragma unroll
        for (int s = 0; s < NSTG; s++){
            asm volatile("mbarrier.init.shared.b64 [%0], %1;" :: "r"(mb + s*8), "r"(1) : "memory");
            asm volatile("mbarrier.init.shared.b64 [%0], %1;" :: "r"(mb + 24 + s*8), "r"(4) : "memory");
        }
    }
    __syncthreads();

    uint32_t lh16 = (uint32_t)(lane >> 4) << 4;
    uint32_t lb16 = (uint32_t)((lane >> 3) & 1) << 4;
    uint32_t aPre[4], aSwm[4], bPre[4], bSwm[4];
    #pragma unroll
    for (int mi = 0; mi < 4; mi++){
        int row = wm*64 + mi*16 + (lane & 15);
        aPre[mi] = (uint32_t)row*128;
        aSwm[mi] = (uint32_t)(row & 7) << 4;
    }
    #pragma unroll
    for (int nj = 0; nj < 4; nj++){
        int row = wn*64 + nj*16 + ((lane >> 4) << 3) + (lane & 7);
        bPre[nj] = (uint32_t)row*128;
        bSwm[nj] = (uint32_t)(row & 7) << 4;
    }

    auto issue = [&](int G){
        int cc = G / CHK;
        int tl = blockIdx.x + NCTA*cc;
        if (tl >= cap) return;
        int t = G % CHK;
        int s = G % 3;
        int bm = tl >> 4, bn = tl & 15;
        const char* srcA = (const char*)g_Xs + ((size_t)(bm*CHK + t))*ABLK;
        const char* srcB = (const char*)g_Wn + ((size_t)(bn*CHK + t))*BBLK;
        uint32_t fb = mb + s*8;
        uint32_t dA = dbase + s*STG;
        uint32_t dB = dA + ABLK;
        asm volatile("mbarrier.arrive.expect_tx.shared.b64 _, [%0], %1;"
                     :: "r"(fb), "r"((uint32_t)STG) : "memory");
        asm volatile("cp.async.bulk.shared::cta.global.mbarrier::complete_tx::bytes [%0], [%1], %2, [%3];"
                     :: "r"(dA), "l"(srcA), "r"((uint32_t)ABLK), "r"(fb) : "memory");
        asm volatile("cp.async.bulk.shared::cta.global.mbarrier::complete_tx::bytes [%0], [%1], %2, [%3];"
                     :: "r"(dB), "l"(srcB), "r"((uint32_t)BBLK), "r"(fb) : "memory");
    };

    if (tid == 0){
        #pragma unroll
        for (int g = 0; g < NSTG; g++) issue(g);
    }

    int c = 0;
    for (int tile = blockIdx.x; tile < cap; tile += NCTA, c++){
        int bm = tile >> 4, bn = tile & 15;

        float acc[4][8][4];
        #pragma unroll
        for (int i = 0; i < 4; i++)
            #pragma unroll
            for (int j = 0; j < 8; j++)
                #pragma unroll
                for (int r = 0; r < 4; r++) acc[i][j][r] = 0.f;

        for (int t = 0; t < CHK; t++){
            int G = c*CHK + t;
            int s = G % 3;
            uint32_t par = (uint32_t)(G / 3) & 1u;
            mbar_wait(mb + s*8, par);

            uint32_t stA = dbase + s*STG;
            uint32_t stB = stA + ABLK;
            uint32_t afr[2][4][4], bfr[2][4][4];
            #pragma unroll
            for (int mi = 0; mi < 4; mi++)
                ldsm4(afr[0][mi], stA + aPre[mi] + (lh16 ^ aSwm[mi]));
            #pragma unroll
            for (int nj = 0; nj < 4; nj++)
                ldsm4(bfr[0][nj], stB + bPre[nj] + (lb16 ^ bSwm[nj]));

            #pragma unroll
            for (int ks = 0; ks < 4; ks++){
                int cur = ks & 1, nxt = cur ^ 1;
                if (ks < 3){
                    uint32_t ca = (uint32_t)((ks+1)*32) + lh16;
                    uint32_t cb = (uint32_t)((ks+1)*32) + lb16;
                    #pragma unroll
                    for (int mi = 0; mi < 4; mi++)
                        ldsm4(afr[nxt][mi], stA + aPre[mi] + (ca ^ aSwm[mi]));
                    #pragma unroll
                    for (int nj = 0; nj < 4; nj++)
                        ldsm4(bfr[nxt][nj], stB + bPre[nj] + (cb ^ bSwm[nj]));
                } else {
                    if (lane == 0)
                        asm volatile("mbarrier.arrive.shared.b64 _, [%0];" :: "r"(mb + 24 + s*8) : "memory");
                }
                #pragma unroll
                for (int mi = 0; mi < 4; mi++){
                    #pragma unroll
                    for (int nj = 0; nj < 4; nj++){
                        mma16816(acc[mi][2*nj],   afr[cur][mi], bfr[cur][nj][0], bfr[cur][nj][1]);
                        mma16816(acc[mi][2*nj+1], afr[cur][mi], bfr[cur][nj][2], bfr[cur][nj][3]);
                    }
                }
            }

            if (tid == 0){
                mbar_wait(mb + 24 + s*8, par);
                issue(G + NSTG);
            }
        }

        int colbase = bn*128 + wn*64;
        #pragma unroll
        for (int mi = 0; mi < 4; mi++){
            int r0 = bm*128 + wm*64 + mi*16 + (lane >> 2);
            __half* out0 = g_preh + (size_t)r0*NG2 + colbase;
            __half* out1 = g_preh + (size_t)(r0+8)*NG2 + colbase;
            #pragma unroll
            for (int nj = 0; nj < 8; nj++){
                int col = nj*8 + (lane & 3)*2;
                *(__half2*)(out0 + col) = __floats2half2_rn(acc[mi][nj][0], acc[mi][nj][1]);
                *(__half2*)(out1 + col) = __floats2half2_rn(acc[mi][nj][2], acc[mi][nj][3]);
            }
        }
    }
}

// activations + state update, warp-per-row; also writes hh fp16 into Xs seg2
__global__ void __launch_bounds__(256) k_act(const float* cs_ext, int l){
    const float* cs = cs_ext ? cs_ext : g_cs[0];
    const float* scs_p = g_scs[l];
    float* cs_q = g_cs[l];
    float* hh_q = g_hh[l];
    int t = threadIdx.x, wid = t >> 5, lane = t & 31;
    int m = blockIdx.x*8 + wid;
    int b = m / Ss, s = m % Ss;
    int h0 = lane*8;
    const __half* pr = g_preh + (size_t)m*NG2;
    const float* bias = g_biasmat + (size_t)b*NG;

    float eg[5][8];
    float esum = 0.f;
    #pragma unroll
    for (int g = 0; g < 5; g++){
        __align__(16) __half hb[8];
        *(uint4*)hb = *(const uint4*)(pr + g*Hh + h0);
        float4 b0 = *(const float4*)(bias + g*Hh + h0);
        float4 b1 = *(const float4*)(bias + g*Hh + h0 + 4);
        float bb[8] = {b0.x,b0.y,b0.z,b0.w,b1.x,b1.y,b1.z,b1.w};
        #pragma unroll
        for (int j = 0; j < 8; j++){
            float x = __half2float(hb[j]) + bb[j];
            float v = __fdividef(1.f, 1.f + __expf(-x));
            eg[g][j] = __expf(v);
            esum += eg[g][j];
        }
    }
    float inv = __fdividef(1.f, warp_sum(esum));

    __align__(16) __half h5[8], h6[8];
    *(uint4*)h5 = *(const uint4*)(pr + 5*Hh + h0);
    *(uint4*)h6 = *(const uint4*)(pr + 6*Hh + h0);
    float4 b50 = *(const float4*)(bias + 5*Hh + h0);
    float4 b51 = *(const float4*)(bias + 5*Hh + h0 + 4);
    float4 b60 = *(const float4*)(bias + 6*Hh + h0);
    float4 b61 = *(const float4*)(bias + 6*Hh + h0 + 4);
    float bb5[8] = {b50.x,b50.y,b50.z,b50.w,b51.x,b51.y,b51.z,b51.w};
    float bb6[8] = {b60.x,b60.y,b60.z,b60.w,b61.x,b61.y,b61.z,b61.w};

    float cbv[8], cav[8], csm[8], scsv[8];
    #pragma unroll
    for (int j = 0; j < 8; j++){ cbv[j] = 0.f; cav[j] = 0.f; }
    auto add8 = [&](float* dst, const float* pp){
        float4 a = *(const float4*)pp;
        float4 b2 = *(const float4*)(pp + 4);
        dst[0]+=a.x; dst[1]+=a.y; dst[2]+=a.z; dst[3]+=a.w;
        dst[4]+=b2.x; dst[5]+=b2.y; dst[6]+=b2.z; dst[7]+=b2.w;
    };
    if (s >= 1)   add8(cbv, cs + (size_t)(m-1)*Hh + h0);
    if (s >= 2)   add8(cbv, cs + (size_t)(m-2)*Hh + h0);
    if (s+1 < Ss) add8(cav, cs + (size_t)(m+1)*Hh + h0);
    if (s+2 < Ss) add8(cav, cs + (size_t)(m+2)*Hh + h0);
    {
        float4 a = *(const float4*)(cs + (size_t)m*Hh + h0);
        float4 b2 = *(const float4*)(cs + (size_t)m*Hh + h0 + 4);
        csm[0]=a.x; csm[1]=a.y; csm[2]=a.z; csm[3]=a.w;
        csm[4]=b2.x; csm[5]=b2.y; csm[6]=b2.z; csm[7]=b2.w;
        float4 c2 = *(const float4*)(scs_p + b*Hh + h0);
        float4 d2 = *(const float4*)(scs_p + b*Hh + h0 + 4);
        scsv[0]=c2.x; scsv[1]=c2.y; scsv[2]=c2.z; scsv[3]=c2.w;
        scsv[4]=d2.x; scsv[5]=d2.y; scsv[6]=d2.z; scsv[7]=d2.w;
    }
    float ncsv[8], nhhv[8];
    #pragma unroll
    for (int j = 0; j < 8; j++){
        float og = __fdividef(1.f, 1.f + __expf(-(__half2float(h5[j]) + bb5[j])));
        float u  = tanhf(__half2float(h6[j]) + bb6[j]);
        float ncs = eg[1][j]*inv*cbv[j] + eg[3][j]*inv*csm[j] + eg[2][j]*inv*cav[j]
                  + eg[4][j]*inv*scsv[j] + eg[0][j]*inv*u;
        ncsv[j] = ncs;
        nhhv[j] = og * tanhf(ncs);
    }
    float* dc = cs_q + (size_t)m*Hh + h0;
    float* dh = hh_q + (size_t)m*Hh + h0;
    *(float4*)dc     = make_float4(ncsv[0],ncsv[1],ncsv[2],ncsv[3]);
    *(float4*)(dc+4) = make_float4(ncsv[4],ncsv[5],ncsv[6],ncsv[7]);
    *(float4*)dh     = make_float4(nhhv[0],nhhv[1],nhhv[2],nhhv[3]);
    *(float4*)(dh+4) = make_float4(nhhv[4],nhhv[5],nhhv[6],nhhv[7]);
    // also write hh segment (cols 512..767) of Xs in fp16 for the next layer's GEMM
    store_seg8(m >> 7, m & 127, 512 + h0, nhhv);
}

// output head; 1024 threads, K split
__global__ void __launch_bounds__(1024) k_head(const float* __restrict__ b1,
                       const float* __restrict__ Wout, const float* __restrict__ bout,
                       float* __restrict__ out, int out_size){
    __shared__ float sa[Hh], ssv[Hh], conc[Hh], fc[5];
    __shared__ float pc[4][Hh];
    __shared__ float lse;
    int b = blockIdx.x, t = threadIdx.x, h = t & 255, qd = t >> 8;
    const float* hh = g_hh[1];
    float av = 0.f;
    for (int s2 = 0; s2 < 128; s2++) av += hh[(size_t)(b*Ss + qd*128 + s2)*Hh + h];
    pc[qd][h] = av;
    if (t < 256) ssv[h] = g_sv[0][b*Hh + h];
    __syncthreads();
    if (t < 256) sa[h] = (pc[0][h]+pc[1][h]+pc[2][h]+pc[3][h]) * (1.f/Ss);
    __syncthreads();
    float c = 0.f;
    int k0 = qd*128;
    #pragma unroll 4
    for (int k2 = 0; k2 < 128; k2++){
        int kk = k0 + k2;
        float src = (kk < 256) ? sa[kk] : ssv[kk-256];
        c += src * g_W1t[kk*Hh + h];
    }
    pc[qd][h] = c;
    __syncthreads();
    if (t < 256) conc[h] = b1[h] + pc[0][h]+pc[1][h]+pc[2][h]+pc[3][h];
    __syncthreads();
    if (t < 5){
        float f = bout[t];
        const float* wo = Wout + (size_t)t*Hh;
        for (int k = 0; k < Hh; k++) f += conc[k]*wo[k];
        fc[t] = f;
    }
    __syncthreads();
    if (t == 0){
        float mx = fc[0];
        #pragma unroll
        for (int i = 1; i < 5; i++) mx = fmaxf(mx, fc[i]);
        float sum = 0.f;
        #pragma unroll
        for (int i = 0; i < 5; i++) sum += expf(fc[i] - mx);
        lse = mx + logf(sum);
    }
    __syncthreads();
    if (t < 5 && out_size >= Bb*5) out[b*5 + t] = fc[t] - lse;
    if (t < 256 && out_size >= Bb*5 + Bb*Hh) out[Bb*5 + b*Hh + h] = ssv[h];
}

// ---------------- host ----------------
extern "C" void kernel_launch(void* const* d_in, const int* in_sizes, int n_in,
                              void* d_out, int out_size){
    const int*   idx       = (const int*)  d_in[0];
    const float* hh0       = (const float*)d_in[2];
    const float* cs0       = (const float*)d_in[3];
    const float* embed     = (const float*)d_in[4];
    const float* W_lr      = (const float*)d_in[5];
    const float* W_c       = (const float*)d_in[6];
    const float* W_x       = (const float*)d_in[7];
    const float* W_g       = (const float*)d_in[8];
    const float* gate_bias = (const float*)d_in[9];
    const float* W_fg_g    = (const float*)d_in[10];
    const float* W_fg_h    = (const float*)d_in[11];
    const float* W_fgi_g   = (const float*)d_in[12];
    const float* W_fgi_h   = (const float*)d_in[13];
    const float* W_og_g    = (const float*)d_in[14];
    const float* W_og_h    = (const float*)d_in[15];
    const float* b_fg      = (const float*)d_in[16];
    const float* b_fgi     = (const float*)d_in[17];
    const float* W1        = (const float*)d_in[18];
    const float* b1        = (const float*)d_in[19];
    const float* Wout      = (const float*)d_in[20];
    const float* bout      = (const float*)d_in[21];
    float* out = (float*)d_out;

    cudaFuncSetAttribute(k_mma, cudaFuncAttributeMaxDynamicSharedMemorySize, SMEM_MMA);

    k_wsplit<<<NG2, 128>>>(W_lr, W_c, W_x, W_fgi_h);
    k_wgt<<<dim3(Hh, 7), Hh>>>(W_g);
    k_wsmt<<<dim3(Hh, 5), Hh>>>(W_fg_g, W_fg_h, W_og_g, W_og_h, W_fgi_g);
    k_w1t<<<512, Hh>>>(W1);
    k_wvseg<<<BS/32, 1024>>>(idx, embed);
    k_hhseg<<<BS/32, 1024>>>(hh0);

    for (int l = 0; l < 2; l++){
        const float* hh_ext = (l == 0) ? hh0 : nullptr;
        const float* cs_ext = (l == 0) ? cs0 : nullptr;
        k_buildXs01<<<BS/16, 1024>>>(hh_ext);
        k_small<<<Bb, 1024>>>(b_fg, gate_bias, hh_ext, cs_ext, l);
        k_mma<<<NCTA, 128, SMEM_MMA>>>(NTILE);
        k_fgi<<<BS/8, 256>>>(b_fgi, cs_ext);
        k_scsbias<<<Bb, 1024>>>(gate_bias, l);
        k_act<<<BS/8, 256>>>(cs_ext, l);
    }
    k_head<<<Bb, 1024>>>(b1, Wout, bout, out, out_size);
}

// round 14
// speedup vs baseline: 1.1840x; 1.1840x over previous
#include <cuda_runtime.h>
#include <cuda_fp16.h>
#include <math.h>
#include <stdint.h>

#define Bb 32
#define Ss 512
#define Hh 256
#define BS (Bb*Ss)          // 16384 rows
#define NG 1792             // 7 gates * 256 (biasmat width)
#define NG2 2048            // GEMM N: 7 gates + fgi projection
#define CHK 16              // K chunks (64 cols) : K = 1024, fp16 hi only
#define ABLK (128*128)      // A chunk block bytes = 16KB
#define BBLK (128*128)      // B chunk block bytes = 16KB
#define NSTG 3
#define STG (ABLK + BBLK)   // 32KB
#define SMEM_MMA (1024 + NSTG*STG + 64)
#define NTILE 2048          // 16 (n) x 128 (m)
#define NCTA 296

// ---------------- scratch (device globals; no allocation allowed) ----------------
__device__ float g_hh[2][BS*Hh];
__device__ float g_cs[2][BS*Hh];
__device__ float g_sv[2][Bb*Hh];
__device__ float g_scs[2][Bb*Hh];
__device__ float g_fgsm[Bb*Hh];
__device__ float g_ogg[Bb*Hh];
__device__ float g_svproj[Bb*Hh];
__device__ float g_biasmat[Bb*NG];
__device__ __half g_preh[(size_t)BS*NG2];     // fp16 pre-activations (67MB)
__device__ float g_sc[BS*Hh];
__device__ float g_Wgt[Hh*NG];                // W_g transposed  [k][g*256+h]
__device__ float g_WsmT[5][Hh*Hh];            // transposed small gates
__device__ float g_W1t[512*Hh];               // W1^T [k][h]
// A: [128 mtiles][16 chunks][128 rows][64 cols] fp16 hi, pre-swizzled (32MB)
__device__ __align__(256) __half g_Xs[(size_t)128*16*128*64];
// B: [16 ntiles][16 chunks][128 rows][64 cols] fp16 hi, pre-swizzled (4MB, L2-resident)
__device__ __align__(256) __half g_Wn[(size_t)16*16*128*64];

__device__ __forceinline__ float sigmoidf(float x){ return 1.f/(1.f+expf(-x)); }

__device__ __forceinline__ uint32_t smem_u32(const void* p){
    uint32_t a;
    asm("{ .reg .u64 t; cvta.to.shared.u64 t, %1; cvt.u32.u64 %0, t; }" : "=r"(a) : "l"(p));
    return a;
}

__device__ __forceinline__ void ldsm4(uint32_t (&r)[4], uint32_t a){
    asm volatile("ldmatrix.sync.aligned.m8n8.x4.shared.b16 {%0,%1,%2,%3}, [%4];"
        : "=r"(r[0]), "=r"(r[1]), "=r"(r[2]), "=r"(r[3]) : "r"(a));
}

__device__ __forceinline__ void mma16816(float (&c)[4], const uint32_t (&a)[4],
                                         uint32_t b0, uint32_t b1){
    asm volatile("mma.sync.aligned.m16n8k16.row.col.f32.f16.f16.f32 "
        "{%0,%1,%2,%3}, {%4,%5,%6,%7}, {%8,%9}, {%0,%1,%2,%3};"
        : "+f"(c[0]), "+f"(c[1]), "+f"(c[2]), "+f"(c[3])
        : "r"(a[0]), "r"(a[1]), "r"(a[2]), "r"(a[3]), "r"(b0), "r"(b1));
}

__device__ __forceinline__ void mbar_wait(uint32_t mbar, uint32_t parity){
    uint32_t done;
    asm volatile("{\n\t.reg .pred p;\n\tmbarrier.try_wait.parity.acquire.cta.shared::cta.b64 p, [%1], %2;\n\tselp.b32 %0, 1, 0, p;\n\t}"
        : "=r"(done) : "r"(mbar), "r"(parity) : "memory");
    while (!done){
        asm volatile("{\n\t.reg .pred p;\n\tmbarrier.try_wait.parity.acquire.cta.shared::cta.b64 p, [%1], %2, 0x989680;\n\tselp.b32 %0, 1, 0, p;\n\t}"
            : "=r"(done) : "r"(mbar), "r"(parity) : "memory");
    }
}

__device__ __forceinline__ float warp_sum(float v){
    #pragma unroll
    for (int o = 16; o > 0; o >>= 1) v += __shfl_xor_sync(0xffffffffu, v, o);
    return v;
}

// ---------------- setup kernels ----------------
// W rows -> fp16, chunked pre-swizzled; n in [1792,2048) = fgi projection columns
__global__ void k_wsplit(const float* __restrict__ W_lr, const float* __restrict__ W_c,
                         const float* __restrict__ W_x, const float* __restrict__ W_fgi_h){
    int n = blockIdx.x;            // 0..2047
    int ntile = n >> 7, r = n & 127;
    int k0 = threadIdx.x * 8;      // 128 threads
    float4 a = make_float4(0.f,0.f,0.f,0.f), b = a;
    if (n < NG){
        int g = n >> 8, h = n & 255;
        const float* src;
        if (k0 < 512)      src = W_lr + ((size_t)g*Hh + h)*512 + k0;
        else if (k0 < 768) src = W_c  + ((size_t)g*Hh + h)*Hh + (k0-512);
        else               src = W_x  + ((size_t)g*Hh + h)*Hh + (k0-768);
        a = *(const float4*)src;
        b = *(const float4*)(src + 4);
    } else if (k0 >= 512 && k0 < 768){
        int h = n - NG;
        const float* src = W_fgi_h + (size_t)h*Hh + (k0-512);
        a = *(const float4*)src;
        b = *(const float4*)(src + 4);
    }
    __align__(16) __half o[8];
    o[0]=__float2half_rn(a.x); o[1]=__float2half_rn(a.y);
    o[2]=__float2half_rn(a.z); o[3]=__float2half_rn(a.w);
    o[4]=__float2half_rn(b.x); o[5]=__float2half_rn(b.y);
    o[6]=__float2half_rn(b.z); o[7]=__float2half_rn(b.w);
    int chunk = k0 >> 6, within = k0 & 63;
    uint32_t cb = ((uint32_t)within*2) ^ ((uint32_t)(r & 7) << 4);
    char* dst = (char*)g_Wn + ((size_t)(ntile*CHK + chunk))*BBLK + (size_t)r*128 + cb;
    *(uint4*)dst = *(const uint4*)o;
}

__global__ void k_wgt(const float* __restrict__ W_g){
    int k = blockIdx.x, g = blockIdx.y, h = threadIdx.x;
    g_Wgt[(size_t)k*NG + g*Hh + h] = W_g[((size_t)(g*Hh+h))*Hh + k];
}

__global__ void k_wsmt(const float* __restrict__ W_fg_g, const float* __restrict__ W_fg_h,
                       const float* __restrict__ W_og_g, const float* __restrict__ W_og_h,
                       const float* __restrict__ W_fgi_g){
    int k = blockIdx.x, which = blockIdx.y, h = threadIdx.x;
    const float* src = (which == 0) ? W_fg_g : (which == 1) ? W_fg_h :
                       (which == 2) ? W_og_g : (which == 3) ? W_og_h : W_fgi_g;
    g_WsmT[which][k*Hh + h] = src[(size_t)h*Hh + k];
}

__global__ void k_w1t(const float* __restrict__ W1){
    int k = blockIdx.x, h = threadIdx.x;
    g_W1t[k*Hh + h] = W1[(size_t)h*512 + k];
}

// ---------------- per-layer kernels ----------------
// small sentence gates; 1024 threads, K split; layer0 computes avgs from hh0/cs0
__global__ void __launch_bounds__(1024) k_small(const float* __restrict__ b_fg,
                        const float* __restrict__ gate_bias,
                        const float* hh_ext, const float* cs_ext, int p){
    __shared__ float ssv[Hh], sav[Hh];
    __shared__ float pf[4][Hh], po[4][Hh], psp[4][Hh];
    __shared__ float red[32];
    int b = blockIdx.x, t = threadIdx.x, h = t & 255, qd = t >> 8;
    const float* hh = hh_ext ? hh_ext : g_hh[p];
    float av = 0.f;
    for (int s2 = 0; s2 < 128; s2++) av += hh[(size_t)(b*Ss + qd*128 + s2)*Hh + h];
    pf[qd][h] = av;
    if (cs_ext){
        float cv = 0.f;
        for (int s2 = 0; s2 < 128; s2++) cv += cs_ext[(size_t)(b*Ss + qd*128 + s2)*Hh + h];
        po[qd][h] = cv;
    } else {
        if (t < 256) ssv[h] = g_sv[p][b*Hh+h];
    }
    __syncthreads();
    if (t < 256){
        sav[h] = (pf[0][h]+pf[1][h]+pf[2][h]+pf[3][h]) * (1.f/Ss);
        if (cs_ext){
            g_scs[p][b*Hh+h] = (po[0][h]+po[1][h]+po[2][h]+po[3][h]) * (1.f/Ss);
            ssv[h] = sav[h];                          // sv0 = avg(hh0)
        }
    }
    __syncthreads();
    float f = 0.f, o = 0.f, sp = 0.f;
    int k0 = qd*64;
    #pragma unroll 4
    for (int k = k0; k < k0+64; k++){
        float s = ssv[k], a = sav[k];
        int off = k*Hh + h;
        f  += s*g_WsmT[0][off] + a*g_WsmT[1][off];
        o  += s*g_WsmT[2][off] + a*g_WsmT[3][off];
        sp += s*g_WsmT[4][off];
    }
    pf[qd][h] = f; po[qd][h] = o; psp[qd][h] = sp;
    __syncthreads();
    float e = 0.f;
    if (t < 256){
        f  = pf[0][h]+pf[1][h]+pf[2][h]+pf[3][h] + b_fg[h];
        o  = po[0][h]+po[1][h]+po[2][h]+po[3][h] + gate_bias[5*Hh + h];
        sp = psp[0][h]+psp[1][h]+psp[2][h]+psp[3][h];
        f = sigmoidf(f);
        g_ogg[b*Hh+h]    = sigmoidf(o);
        g_svproj[b*Hh+h] = sp;
        e = expf(f);
    }
    int lane = t & 31, w = t >> 5;
    float r = warp_sum(e);
    if (lane == 0) red[w] = r;
    __syncthreads();
    if (t < 32){
        float rr = red[t];
        #pragma unroll
        for (int o2 = 16; o2 > 0; o2 >>= 1) rr += __shfl_xor_sync(0xffffffffu, rr, o2);
        if (t == 0) red[0] = rr;
    }
    __syncthreads();
    if (t < 256) g_fgsm[b*Hh+h] = e / red[0];
}

// fgi softmax, warp-per-row (8 rows/block), shuffle-only reduce
__global__ void __launch_bounds__(256) k_fgi(const float* __restrict__ b_fgi,
                                             const float* cs_ext, int p){
    const float* cs_p = cs_ext ? cs_ext : g_cs[p];
    int t = threadIdx.x, wid = t >> 5, lane = t & 31;
    int m = blockIdx.x*8 + wid;
    int b = m / Ss;
    int h0 = lane*8;
    __align__(16) __half hbuf[8];
    *(uint4*)hbuf = *(const uint4*)(g_preh + (size_t)m*NG2 + NG + h0);
    float4 s0 = *(const float4*)(g_svproj + b*Hh + h0);
    float4 s1 = *(const float4*)(g_svproj + b*Hh + h0 + 4);
    float4 f0 = *(const float4*)(b_fgi + h0);
    float4 f1 = *(const float4*)(b_fgi + h0 + 4);
    float sp[8] = {s0.x,s0.y,s0.z,s0.w,s1.x,s1.y,s1.z,s1.w};
    float bf[8] = {f0.x,f0.y,f0.z,f0.w,f1.x,f1.y,f1.z,f1.w};
    float e[8]; float esum = 0.f;
    #pragma unroll
    for (int j = 0; j < 8; j++){
        float x = __half2float(hbuf[j]) + sp[j] + bf[j];
        e[j] = __expf(__fdividef(1.f, 1.f + __expf(-x)));
        esum += e[j];
    }
    float inv = __fdividef(1.f, warp_sum(esum));
    const float* csr = cs_p + (size_t)m*Hh + h0;
    float4 c0 = *(const float4*)csr;
    float4 c1 = *(const float4*)(csr + 4);
    float cv[8] = {c0.x,c0.y,c0.z,c0.w,c1.x,c1.y,c1.z,c1.w};
    float4 o0, o1;
    o0.x = e[0]*inv*cv[0]; o0.y = e[1]*inv*cv[1]; o0.z = e[2]*inv*cv[2]; o0.w = e[3]*inv*cv[3];
    o1.x = e[4]*inv*cv[4]; o1.y = e[5]*inv*cv[5]; o1.z = e[6]*inv*cv[6]; o1.w = e[7]*inv*cv[7];
    float* dst = g_sc + (size_t)m*Hh + h0;
    *(float4*)dst = o0;
    *(float4*)(dst + 4) = o1;
}

// new_scs + new_sv; 1024 threads, S split across 4 groups
__global__ void __launch_bounds__(1024) k_scs(int p, int q){
    __shared__ float ps[4][Hh];
    int b = blockIdx.x, t = threadIdx.x, h = t & 255, qd = t >> 8;
    float acc = 0.f;
    for (int s2 = 0; s2 < 128; s2++) acc += g_sc[(size_t)(b*Ss + qd*128 + s2)*Hh + h];
    ps[qd][h] = acc;
    __syncthreads();
    if (t < 256){
        int i = b*Hh + h;
        float ns = g_fgsm[i]*g_scs[p][i] + ps[0][h]+ps[1][h]+ps[2][h]+ps[3][h];
        g_scs[q][i] = ns;
        g_sv[q][i]  = g_ogg[i] * tanhf(ns);
    }
}

// biasmat = new_sv @ W_g^T + gate_bias; grid (7, Bb), 1024 threads, K split
__global__ void __launch_bounds__(1024) k_biasmat(const float* __restrict__ gate_bias, int q){
    __shared__ float ssv[Hh];
    __shared__ float pa[4][Hh];
    int g = blockIdx.x, b = blockIdx.y, t = threadIdx.x, h = t & 255, qd = t >> 8;
    if (t < 256) ssv[h] = g_sv[q][b*Hh + h];
    __syncthreads();
    float a = 0.f;
    int k0 = qd*64;
    #pragma unroll 4
    for (int k = k0; k < k0+64; k++)
        a += ssv[k] * g_Wgt[(size_t)k*NG + g*Hh + h];
    pa[qd][h] = a;
    __syncthreads();
    if (t < 256)
        g_biasmat[(size_t)b*NG + g*Hh + h] = gate_bias[g*Hh+h] + pa[0][h]+pa[1][h]+pa[2][h]+pa[3][h];
}

// X = [hb | ha | hh | wv] -> fp16 hi, chunked pre-swizzled; 8 rows per 1024-thr block
__global__ void __launch_bounds__(1024) k_buildXs(const int* __restrict__ idx,
                                                  const float* __restrict__ embed,
                                                  const float* hh_ext, int p){
    const float* hh = hh_ext ? hh_ext : g_hh[p];
    int t = threadIdx.x;
    int m = blockIdx.x*8 + (t >> 7);
    int mtile = m >> 7, r = m & 127, s = m % Ss;
    int sc0 = (t & 127) * 8;              // 0..1023
    int chunk = sc0 >> 6, within = sc0 & 63;
    int seg = sc0 >> 8, h0 = sc0 & 255;
    float v[8];
    #pragma unroll
    for (int j = 0; j < 8; j++) v[j] = 0.f;
    auto add8 = [&](const float* pp){
        float4 a = *(const float4*)pp;
        float4 b = *(const float4*)(pp + 4);
        v[0]+=a.x; v[1]+=a.y; v[2]+=a.z; v[3]+=a.w;
        v[4]+=b.x; v[5]+=b.y; v[6]+=b.z; v[7]+=b.w;
    };
    if (seg == 0){
        if (s >= 1) add8(hh + (size_t)(m-1)*Hh + h0);
        if (s >= 2) add8(hh + (size_t)(m-2)*Hh + h0);
    } else if (seg == 1){
        if (s+1 < Ss) add8(hh + (size_t)(m+1)*Hh + h0);
        if (s+2 < Ss) add8(hh + (size_t)(m+2)*Hh + h0);
    } else if (seg == 2){
        add8(hh + (size_t)m*Hh + h0);
    } else {
        add8(embed + (size_t)idx[m]*Hh + h0);
    }
    __align__(16) __half o[8];
    #pragma unroll
    for (int j = 0; j < 8; j++) o[j] = __float2half_rn(v[j]);
    uint32_t cb = ((uint32_t)within*2) ^ ((uint32_t)(r & 7) << 4);
    char* dst = (char*)g_Xs + ((size_t)(mtile*CHK + chunk))*ABLK + (size_t)r*128 + cb;
    *(uint4*)dst = *(const uint4*)o;
}

// ---------------- bulk-copy HMMA GEMM: preh = X @ Wn^T ----------------
// persistent, tile 128x128, 4 warps of 64x64, 3-stage bulk+mbarrier, 2 CTAs/SM,
// fragment double-buffering across ks + early empty-arrive after last LDSM
__global__ void __launch_bounds__(128,2) k_mma(int cap){
    extern __shared__ char smc[];
    uint32_t sb = smem_u32(smc);
    uint32_t dbase = (sb + 1023) & ~1023u;
    uint32_t mb = dbase + NSTG*STG;
    int tid = threadIdx.x, wid = tid >> 5, lane = tid & 31;
    int wm = wid >> 1, wn = wid & 1;     // warp tile 64(M) x 64(N)

    if (tid == 0){
        #pragma unroll
        for (int s = 0; s < NSTG; s++){
            asm volatile("mbarrier.init.shared.b64 [%0], %1;" :: "r"(mb + s*8), "r"(1) : "memory");
            asm volatile("mbarrier.init.shared.b64 [%0], %1;" :: "r"(mb + 24 + s*8), "r"(4) : "memory");
        }
    }
    __syncthreads();

    uint32_t lh16 = (uint32_t)(lane >> 4) << 4;
    uint32_t lb16 = (uint32_t)((lane >> 3) & 1) << 4;
    uint32_t aPre[4], aSwm[4], bPre[4], bSwm[4];
    #pragma unroll
    for (int mi = 0; mi < 4; mi++){
        int row = wm*64 + mi*16 + (lane & 15);
        aPre[mi] = (uint32_t)row*128;
        aSwm[mi] = (uint32_t)(row & 7) << 4;
    }
    #pragma unroll
    for (int nj = 0; nj < 4; nj++){
        int row = wn*64 + nj*16 + ((lane >> 4) << 3) + (lane & 7);
        bPre[nj] = (uint32_t)row*128;
        bSwm[nj] = (uint32_t)(row & 7) << 4;
    }

    auto issue = [&](int G){
        int cc = G / CHK;
        int tl = blockIdx.x + NCTA*cc;
        if (tl >= cap) return;
        int t = G % CHK;
        int s = G % 3;
        int bm = tl >> 4, bn = tl & 15;
        const char* srcA = (const char*)g_Xs + ((size_t)(bm*CHK + t))*ABLK;
        const char* srcB = (const char*)g_Wn + ((size_t)(bn*CHK + t))*BBLK;
        uint32_t fb = mb + s*8;
        uint32_t dA = dbase + s*STG;
        uint32_t dB = dA + ABLK;
        asm volatile("mbarrier.arrive.expect_tx.shared.b64 _, [%0], %1;"
                     :: "r"(fb), "r"((uint32_t)STG) : "memory");
        asm volatile("cp.async.bulk.shared::cta.global.mbarrier::complete_tx::bytes [%0], [%1], %2, [%3];"
                     :: "r"(dA), "l"(srcA), "r"((uint32_t)ABLK), "r"(fb) : "memory");
        asm volatile("cp.async.bulk.shared::cta.global.mbarrier::complete_tx::bytes [%0], [%1], %2, [%3];"
                     :: "r"(dB), "l"(srcB), "r"((uint32_t)BBLK), "r"(fb) : "memory");
    };

    if (tid == 0){
        #pragma unroll
        for (int g = 0; g < NSTG; g++) issue(g);
    }

    int c = 0;
    for (int tile = blockIdx.x; tile < cap; tile += NCTA, c++){
        int bm = tile >> 4, bn = tile & 15;

        float acc[4][8][4];
        #pragma unroll
        for (int i = 0; i < 4; i++)
            #pragma unroll
            for (int j = 0; j < 8; j++)
                #pragma unroll
                for (int r = 0; r < 4; r++) acc[i][j][r] = 0.f;

        for (int t = 0; t < CHK; t++){
            int G = c*CHK + t;
            int s = G % 3;
            uint32_t par = (uint32_t)(G / 3) & 1u;
            mbar_wait(mb + s*8, par);

            uint32_t stA = dbase + s*STG;
            uint32_t stB = stA + ABLK;
            uint32_t afr[2][4][4], bfr[2][4][4];
            #pragma unroll
            for (int mi = 0; mi < 4; mi++)
                ldsm4(afr[0][mi], stA + aPre[mi] + (lh16 ^ aSwm[mi]));
            #pragma unroll
            for (int nj = 0; nj < 4; nj++)
                ldsm4(bfr[0][nj], stB + bPre[nj] + (lb16 ^ bSwm[nj]));

            #pragma unroll
            for (int ks = 0; ks < 4; ks++){
                int cur = ks & 1, nxt = cur ^ 1;
                if (ks < 3){
                    uint32_t ca = (uint32_t)((ks+1)*32) + lh16;
                    uint32_t cb = (uint32_t)((ks+1)*32) + lb16;
                    #pragma unroll
                    for (int mi = 0; mi < 4; mi++)
                        ldsm4(afr[nxt][mi], stA + aPre[mi] + (ca ^ aSwm[mi]));
                    #pragma unroll
                    for (int nj = 0; nj < 4; nj++)
                        ldsm4(bfr[nxt][nj], stB + bPre[nj] + (cb ^ bSwm[nj]));
                } else {
                    if (lane == 0)
                        asm volatile("mbarrier.arrive.shared.b64 _, [%0];" :: "r"(mb + 24 + s*8) : "memory");
                }
                #pragma unroll
                for (int mi = 0; mi < 4; mi++){
                    #pragma unroll
                    for (int nj = 0; nj < 4; nj++){
                        mma16816(acc[mi][2*nj],   afr[cur][mi], bfr[cur][nj][0], bfr[cur][nj][1]);
                        mma16816(acc[mi][2*nj+1], afr[cur][mi], bfr[cur][nj][2], bfr[cur][nj][3]);
                    }
                }
            }

            if (tid == 0){
                mbar_wait(mb + 24 + s*8, par);
                issue(G + NSTG);
            }
        }

        int colbase = bn*128 + wn*64;
        #pragma unroll
        for (int mi = 0; mi < 4; mi++){
            int r0 = bm*128 + wm*64 + mi*16 + (lane >> 2);
            __half* out0 = g_preh + (size_t)r0*NG2 + colbase;
            __half* out1 = g_preh + (size_t)(r0+8)*NG2 + colbase;
            #pragma unroll
            for (int nj = 0; nj < 8; nj++){
                int col = nj*8 + (lane & 3)*2;
                *(__half2*)(out0 + col) = __floats2half2_rn(acc[mi][nj][0], acc[mi][nj][1]);
                *(__half2*)(out1 + col) = __floats2half2_rn(acc[mi][nj][2], acc[mi][nj][3]);
            }
        }
    }
}

// activations + state update, warp-per-row (8 rows/block), shuffle-only reduce
__global__ void __launch_bounds__(256) k_act(const float* cs_ext, int p, int q){
    const float* cs = cs_ext ? cs_ext : g_cs[p];
    int t = threadIdx.x, wid = t >> 5, lane = t & 31;
    int m = blockIdx.x*8 + wid;
    int b = m / Ss, s = m % Ss;
    int h0 = lane*8;
    const __half* pr = g_preh + (size_t)m*NG2;
    const float* bias = g_biasmat + (size_t)b*NG;

    float eg[5][8];
    float esum = 0.f;
    #pragma unroll
    for (int g = 0; g < 5; g++){
        __align__(16) __half hb[8];
        *(uint4*)hb = *(const uint4*)(pr + g*Hh + h0);
        float4 b0 = *(const float4*)(bias + g*Hh + h0);
        float4 b1 = *(const float4*)(bias + g*Hh + h0 + 4);
        float bb[8] = {b0.x,b0.y,b0.z,b0.w,b1.x,b1.y,b1.z,b1.w};
        #pragma unroll
        for (int j = 0; j < 8; j++){
            float x = __half2float(hb[j]) + bb[j];
            float v = __fdividef(1.f, 1.f + __expf(-x));
            eg[g][j] = __expf(v);
            esum += eg[g][j];
        }
    }
    float inv = __fdividef(1.f, warp_sum(esum));

    __align__(16) __half h5[8], h6[8];
    *(uint4*)h5 = *(const uint4*)(pr + 5*Hh + h0);
    *(uint4*)h6 = *(const uint4*)(pr + 6*Hh + h0);
    float4 b50 = *(const float4*)(bias + 5*Hh + h0);
    float4 b51 = *(const float4*)(bias + 5*Hh + h0 + 4);
    float4 b60 = *(const float4*)(bias + 6*Hh + h0);
    float4 b61 = *(const float4*)(bias + 6*Hh + h0 + 4);
    float bb5[8] = {b50.x,b50.y,b50.z,b50.w,b51.x,b51.y,b51.z,b51.w};
    float bb6[8] = {b60.x,b60.y,b60.z,b60.w,b61.x,b61.y,b61.z,b61.w};

    float cbv[8], cav[8], csm[8], scsv[8];
    #pragma unroll
    for (int j = 0; j < 8; j++){ cbv[j] = 0.f; cav[j] = 0.f; }
    auto add8 = [&](float* dst, const float* pp){
        float4 a = *(const float4*)pp;
        float4 b2 = *(const float4*)(pp + 4);
        dst[0]+=a.x; dst[1]+=a.y; dst[2]+=a.z; dst[3]+=a.w;
        dst[4]+=b2.x; dst[5]+=b2.y; dst[6]+=b2.z; dst[7]+=b2.w;
    };
    if (s >= 1)   add8(cbv, cs + (size_t)(m-1)*Hh + h0);
    if (s >= 2)   add8(cbv, cs + (size_t)(m-2)*Hh + h0);
    if (s+1 < Ss) add8(cav, cs + (size_t)(m+1)*Hh + h0);
    if (s+2 < Ss) add8(cav, cs + (size_t)(m+2)*Hh + h0);
    {
        float4 a = *(const float4*)(cs + (size_t)m*Hh + h0);
        float4 b2 = *(const float4*)(cs + (size_t)m*Hh + h0 + 4);
        csm[0]=a.x; csm[1]=a.y; csm[2]=a.z; csm[3]=a.w;
        csm[4]=b2.x; csm[5]=b2.y; csm[6]=b2.z; csm[7]=b2.w;
        float4 c2 = *(const float4*)(g_scs[p] + b*Hh + h0);
        float4 d2 = *(const float4*)(g_scs[p] + b*Hh + h0 + 4);
        scsv[0]=c2.x; scsv[1]=c2.y; scsv[2]=c2.z; scsv[3]=c2.w;
        scsv[4]=d2.x; scsv[5]=d2.y; scsv[6]=d2.z; scsv[7]=d2.w;
    }
    float ncsv[8], nhhv[8];
    #pragma unroll
    for (int j = 0; j < 8; j++){
        float og = __fdividef(1.f, 1.f + __expf(-(__half2float(h5[j]) + bb5[j])));
        float u  = tanhf(__half2float(h6[j]) + bb6[j]);
        float ncs = eg[1][j]*inv*cbv[j] + eg[3][j]*inv*csm[j] + eg[2][j]*inv*cav[j]
                  + eg[4][j]*inv*scsv[j] + eg[0][j]*inv*u;
        ncsv[j] = ncs;
        nhhv[j] = og * tanhf(ncs);
    }
    float* dc = g_cs[q] + (size_t)m*Hh + h0;
    float* dh = g_hh[q] + (size_t)m*Hh + h0;
    *(float4*)dc     = make_float4(ncsv[0],ncsv[1],ncsv[2],ncsv[3]);
    *(float4*)(dc+4) = make_float4(ncsv[4],ncsv[5],ncsv[6],ncsv[7]);
    *(float4*)dh     = make_float4(nhhv[0],nhhv[1],nhhv[2],nhhv[3]);
    *(float4*)(dh+4) = make_float4(nhhv[4],nhhv[5],nhhv[6],nhhv[7]);
}

// output head; 1024 threads, K split
__global__ void __launch_bounds__(1024) k_head(const float* __restrict__ b1,
                       const float* __restrict__ Wout, const float* __restrict__ bout,
                       int p, float* __restrict__ out, int out_size){
    __shared__ float sa[Hh], ssv[Hh], conc[Hh], fc[5];
    __shared__ float pc[4][Hh];
    __shared__ float lse;
    int b = blockIdx.x, t = threadIdx.x, h = t & 255, qd = t >> 8;
    const float* hh = g_hh[p];
    float av = 0.f;
    for (int s2 = 0; s2 < 128; s2++) av += hh[(size_t)(b*Ss + qd*128 + s2)*Hh + h];
    pc[qd][h] = av;
    if (t < 256) ssv[h] = g_sv[p][b*Hh + h];
    __syncthreads();
    if (t < 256) sa[h] = (pc[0][h]+pc[1][h]+pc[2][h]+pc[3][h]) * (1.f/Ss);
    __syncthreads();
    float c = 0.f;
    int k0 = qd*128;
    #pragma unroll 4
    for (int k2 = 0; k2 < 128; k2++){
        int kk = k0 + k2;
        float src = (kk < 256) ? sa[kk] : ssv[kk-256];
        c += src * g_W1t[kk*Hh + h];
    }
    pc[qd][h] = c;
    __syncthreads();
    if (t < 256) conc[h] = b1[h] + pc[0][h]+pc[1][h]+pc[2][h]+pc[3][h];
    __syncthreads();
    if (t < 5){
        float f = bout[t];
        const float* wo = Wout + (size_t)t*Hh;
        for (int k = 0; k < Hh; k++) f += conc[k]*wo[k];
        fc[t] = f;
    }
    __syncthreads();
    if (t == 0){
        float mx = fc[0];
        #pragma unroll
        for (int i = 1; i < 5; i++) mx = fmaxf(mx, fc[i]);
        float sum = 0.f;
        #pragma unroll
        for (int i = 0; i < 5; i++) sum += expf(fc[i] - mx);
        lse = mx + logf(sum);
    }
    __syncthreads();
    if (t < 5 && out_size >= Bb*5) out[b*5 + t] = fc[t] - lse;
    if (t < 256 && out_size >= Bb*5 + Bb*Hh) out[Bb*5 + b*Hh + h] = ssv[h];
}

// ---------------- host ----------------
extern "C" void kernel_launch(void* const* d_in, const int* in_sizes, int n_in,
                              void* d_out, int out_size){
    const int*   idx       = (const int*)  d_in[0];
    const float* hh0       = (const float*)d_in[2];
    const float* cs0       = (const float*)d_in[3];
    const float* embed     = (const float*)d_in[4];
    const float* W_lr      = (const float*)d_in[5];
    const float* W_c       = (const float*)d_in[6];
    const float* W_x       = (const float*)d_in[7];
    const float* W_g       = (const float*)d_in[8];
    const float* gate_bias = (const float*)d_in[9];
    const float* W_fg_g    = (const float*)d_in[10];
    const float* W_fg_h    = (const float*)d_in[11];
    const float* W_fgi_g   = (const float*)d_in[12];
    const float* W_fgi_h   = (const float*)d_in[13];
    const float* W_og_g    = (const float*)d_in[14];
    const float* W_og_h    = (const float*)d_in[15];
    const float* b_fg      = (const float*)d_in[16];
    const float* b_fgi     = (const float*)d_in[17];
    const float* W1        = (const float*)d_in[18];
    const float* b1        = (const float*)d_in[19];
    const float* Wout      = (const float*)d_in[20];
    const float* bout      = (const float*)d_in[21];
    float* out = (float*)d_out;

    cudaFuncSetAttribute(k_mma, cudaFuncAttributeMaxDynamicSharedMemorySize, SMEM_MMA);

    k_wsplit<<<NG2, 128>>>(W_lr, W_c, W_x, W_fgi_h);
    k_wgt<<<dim3(Hh, 7), Hh>>>(W_g);
    k_wsmt<<<dim3(Hh, 5), Hh>>>(W_fg_g, W_fg_h, W_og_g, W_og_h, W_fgi_g);
    k_w1t<<<512, Hh>>>(W1);

    int p = 0;
    for (int layer = 0; layer < 2; layer++){
        int q = 1 - p;
        const float* hh_ext = (layer == 0) ? hh0 : nullptr;
        const float* cs_ext = (layer == 0) ? cs0 : nullptr;
        k_buildXs<<<BS/8, 1024>>>(idx, embed, hh_ext, p);
        k_small<<<Bb, 1024>>>(b_fg, gate_bias, hh_ext, cs_ext, p);
        k_mma<<<NCTA, 128, SMEM_MMA>>>(NTILE);
        k_fgi<<<BS/8, 256>>>(b_fgi, cs_ext, p);
        k_scs<<<Bb, 1024>>>(p, q);
        k_biasmat<<<dim3(7, Bb), 1024>>>(gate_bias, q);
        k_act<<<BS/8, 256>>>(cs_ext, p, q);
        p = q;
    }
    k_head<<<Bb, 1024>>>(b1, Wout, bout, p, out, out_size);
}

// round 15
// speedup vs baseline: 1.2209x; 1.0312x over previous
#include <cuda_runtime.h>
#include <cuda_fp16.h>
#include <math.h>
#include <stdint.h>

#define Bb 32
#define Ss 512
#define Hh 256
#define BS (Bb*Ss)          // 16384 rows
#define NG 1792             // 7 gates * 256 (biasmat width)
#define NG2 2048            // GEMM N: 7 gates + fgi projection
#define CHK 16              // K chunks (64 cols) : K = 1024, fp16 hi only
#define ABLK (128*128)      // A chunk block bytes = 16KB
#define BBLK (128*128)      // B chunk block bytes = 16KB
#define NSTG 3
#define STG (ABLK + BBLK)   // 32KB
#define SMEM_MMA (1024 + NSTG*STG + 64)
#define NTILE 2048          // 16 (n) x 128 (m)
#define NCTA 296
#define FBLK 64             // fgi partial blocks per batch (512/8)

// ---------------- scratch (device globals; no allocation allowed) ----------------
__device__ float g_hh[2][BS*Hh];
__device__ float g_cs[2][BS*Hh];
__device__ float g_sv[2][Bb*Hh];
__device__ float g_scs[2][Bb*Hh];
__device__ float g_fgsm[Bb*Hh];
__device__ float g_ogg[Bb*Hh];
__device__ float g_svproj[Bb*Hh];
__device__ float g_biasmat[Bb*NG];
__device__ __half g_preh[(size_t)BS*NG2];     // fp16 pre-activations (67MB)
__device__ float g_scp[(BS/8)*Hh];            // fgi block partial sums (2MB)
__device__ float g_Wgt[Hh*NG];                // W_g transposed  [k][g*256+h]
__device__ float g_WsmT[5][Hh*Hh];            // transposed small gates
__device__ float g_W1t[512*Hh];               // W1^T [k][h]
// A: [128 mtiles][16 chunks][128 rows][64 cols] fp16 hi, pre-swizzled (32MB)
__device__ __align__(256) __half g_Xs[(size_t)128*16*128*64];
// B: [16 ntiles][16 chunks][128 rows][64 cols] fp16 hi, pre-swizzled (4MB, L2-resident)
__device__ __align__(256) __half g_Wn[(size_t)16*16*128*64];

__device__ __forceinline__ float sigmoidf(float x){ return 1.f/(1.f+expf(-x)); }

__device__ __forceinline__ uint32_t smem_u32(const void* p){
    uint32_t a;
    asm("{ .reg .u64 t; cvta.to.shared.u64 t, %1; cvt.u32.u64 %0, t; }" : "=r"(a) : "l"(p));
    return a;
}

__device__ __forceinline__ void ldsm4(uint32_t (&r)[4], uint32_t a){
    asm volatile("ldmatrix.sync.aligned.m8n8.x4.shared.b16 {%0,%1,%2,%3}, [%4];"
        : "=r"(r[0]), "=r"(r[1]), "=r"(r[2]), "=r"(r[3]) : "r"(a));
}

__device__ __forceinline__ void mma16816(float (&c)[4], const uint32_t (&a)[4],
                                         uint32_t b0, uint32_t b1){
    asm volatile("mma.sync.aligned.m16n8k16.row.col.f32.f16.f16.f32 "
        "{%0,%1,%2,%3}, {%4,%5,%6,%7}, {%8,%9}, {%0,%1,%2,%3};"
        : "+f"(c[0]), "+f"(c[1]), "+f"(c[2]), "+f"(c[3])
        : "r"(a[0]), "r"(a[1]), "r"(a[2]), "r"(a[3]), "r"(b0), "r"(b1));
}

__device__ __forceinline__ void mbar_wait(uint32_t mbar, uint32_t parity){
    uint32_t done;
    asm volatile("{\n\t.reg .pred p;\n\tmbarrier.try_wait.parity.acquire.cta.shared::cta.b64 p, [%1], %2;\n\tselp.b32 %0, 1, 0, p;\n\t}"
        : "=r"(done) : "r"(mbar), "r"(parity) : "memory");
    while (!done){
        asm volatile("{\n\t.reg .pred p;\n\tmbarrier.try_wait.parity.acquire.cta.shared::cta.b64 p, [%1], %2, 0x989680;\n\tselp.b32 %0, 1, 0, p;\n\t}"
            : "=r"(done) : "r"(mbar), "r"(parity) : "memory");
    }
}

__device__ __forceinline__ float warp_sum(float v){
    #pragma unroll
    for (int o = 16; o > 0; o >>= 1) v += __shfl_xor_sync(0xffffffffu, v, o);
    return v;
}

// ---------------- setup kernels ----------------
// W rows -> fp16, chunked pre-swizzled; n in [1792,2048) = fgi projection columns
__global__ void k_wsplit(const float* __restrict__ W_lr, const float* __restrict__ W_c,
                         const float* __restrict__ W_x, const float* __restrict__ W_fgi_h){
    int n = blockIdx.x;            // 0..2047
    int ntile = n >> 7, r = n & 127;
    int k0 = threadIdx.x * 8;      // 128 threads
    float4 a = make_float4(0.f,0.f,0.f,0.f), b = a;
    if (n < NG){
        int g = n >> 8, h = n & 255;
        const float* src;
        if (k0 < 512)      src = W_lr + ((size_t)g*Hh + h)*512 + k0;
        else if (k0 < 768) src = W_c  + ((size_t)g*Hh + h)*Hh + (k0-512);
        else               src = W_x  + ((size_t)g*Hh + h)*Hh + (k0-768);
        a = *(const float4*)src;
        b = *(const float4*)(src + 4);
    } else if (k0 >= 512 && k0 < 768){
        int h = n - NG;
        const float* src = W_fgi_h + (size_t)h*Hh + (k0-512);
        a = *(const float4*)src;
        b = *(const float4*)(src + 4);
    }
    __align__(16) __half o[8];
    o[0]=__float2half_rn(a.x); o[1]=__float2half_rn(a.y);
    o[2]=__float2half_rn(a.z); o[3]=__float2half_rn(a.w);
    o[4]=__float2half_rn(b.x); o[5]=__float2half_rn(b.y);
    o[6]=__float2half_rn(b.z); o[7]=__float2half_rn(b.w);
    int chunk = k0 >> 6, within = k0 & 63;
    uint32_t cb = ((uint32_t)within*2) ^ ((uint32_t)(r & 7) << 4);
    char* dst = (char*)g_Wn + ((size_t)(ntile*CHK + chunk))*BBLK + (size_t)r*128 + cb;
    *(uint4*)dst = *(const uint4*)o;
}

// tiled transpose: in [R][C] -> out [C][R]; grid(C/32, R/32), block(32,8)
__global__ void k_tpose(const float* __restrict__ in, float* __restrict__ out, int R, int C){
    __shared__ float tile[32][33];
    int c0 = blockIdx.x*32, r0 = blockIdx.y*32;
    int tx = threadIdx.x, ty = threadIdx.y;
    #pragma unroll
    for (int i = 0; i < 32; i += 8)
        tile[ty+i][tx] = in[(size_t)(r0+ty+i)*C + c0+tx];
    __syncthreads();
    #pragma unroll
    for (int i = 0; i < 32; i += 8)
        out[(size_t)(c0+ty+i)*R + r0+tx] = tile[tx][ty+i];
}

// 5 small gate matrices 256x256, transposed; grid(8,8,5), block(32,8)
__global__ void k_wsmt(const float* __restrict__ W_fg_g, const float* __restrict__ W_fg_h,
                       const float* __restrict__ W_og_g, const float* __restrict__ W_og_h,
                       const float* __restrict__ W_fgi_g){
    __shared__ float tile[32][33];
    int which = blockIdx.z;
    const float* in = (which == 0) ? W_fg_g : (which == 1) ? W_fg_h :
                      (which == 2) ? W_og_g : (which == 3) ? W_og_h : W_fgi_g;
    float* out = g_WsmT[which];
    int c0 = blockIdx.x*32, r0 = blockIdx.y*32;
    int tx = threadIdx.x, ty = threadIdx.y;
    #pragma unroll
    for (int i = 0; i < 32; i += 8)
        tile[ty+i][tx] = in[(size_t)(r0+ty+i)*Hh + c0+tx];
    __syncthreads();
    #pragma unroll
    for (int i = 0; i < 32; i += 8)
        out[(size_t)(c0+ty+i)*Hh + r0+tx] = tile[tx][ty+i];
}

// ---------------- per-layer kernels ----------------
// small sentence gates; 1024 threads, K split; layer0 computes avgs from hh0/cs0
__global__ void __launch_bounds__(1024) k_small(const float* __restrict__ b_fg,
                        const float* __restrict__ gate_bias,
                        const float* hh_ext, const float* cs_ext, int p){
    __shared__ float ssv[Hh], sav[Hh];
    __shared__ float pf[4][Hh], po[4][Hh], psp[4][Hh];
    __shared__ float red[32];
    int b = blockIdx.x, t = threadIdx.x, h = t & 255, qd = t >> 8;
    const float* hh = hh_ext ? hh_ext : g_hh[p];
    float av = 0.f;
    for (int s2 = 0; s2 < 128; s2++) av += hh[(size_t)(b*Ss + qd*128 + s2)*Hh + h];
    pf[qd][h] = av;
    if (cs_ext){
        float cv = 0.f;
        for (int s2 = 0; s2 < 128; s2++) cv += cs_ext[(size_t)(b*Ss + qd*128 + s2)*Hh + h];
        po[qd][h] = cv;
    } else {
        if (t < 256) ssv[h] = g_sv[p][b*Hh+h];
    }
    __syncthreads();
    if (t < 256){
        sav[h] = (pf[0][h]+pf[1][h]+pf[2][h]+pf[3][h]) * (1.f/Ss);
        if (cs_ext){
            g_scs[p][b*Hh+h] = (po[0][h]+po[1][h]+po[2][h]+po[3][h]) * (1.f/Ss);
            ssv[h] = sav[h];                          // sv0 = avg(hh0)
        }
    }
    __syncthreads();
    float f = 0.f, o = 0.f, sp = 0.f;
    int k0 = qd*64;
    #pragma unroll 4
    for (int k = k0; k < k0+64; k++){
        float s = ssv[k], a = sav[k];
        int off = k*Hh + h;
        f  += s*g_WsmT[0][off] + a*g_WsmT[1][off];
        o  += s*g_WsmT[2][off] + a*g_WsmT[3][off];
        sp += s*g_WsmT[4][off];
    }
    pf[qd][h] = f; po[qd][h] = o; psp[qd][h] = sp;
    __syncthreads();
    float e = 0.f;
    if (t < 256){
        f  = pf[0][h]+pf[1][h]+pf[2][h]+pf[3][h] + b_fg[h];
        o  = po[0][h]+po[1][h]+po[2][h]+po[3][h] + gate_bias[5*Hh + h];
        sp = psp[0][h]+psp[1][h]+psp[2][h]+psp[3][h];
        f = sigmoidf(f);
        g_ogg[b*Hh+h]    = sigmoidf(o);
        g_svproj[b*Hh+h] = sp;
        e = expf(f);
    }
    int lane = t & 31, w = t >> 5;
    float r = warp_sum(e);
    if (lane == 0) red[w] = r;
    __syncthreads();
    if (t < 32){
        float rr = red[t];
        #pragma unroll
        for (int o2 = 16; o2 > 0; o2 >>= 1) rr += __shfl_xor_sync(0xffffffffu, rr, o2);
        if (t == 0) red[0] = rr;
    }
    __syncthreads();
    if (t < 256) g_fgsm[b*Hh+h] = e / red[0];
}

// fgi softmax, warp-per-row (8 rows/block); emits block-partial sum of scores*cs
__global__ void __launch_bounds__(256) k_fgi(const float* __restrict__ b_fgi,
                                             const float* cs_ext, int p){
    __shared__ float sbuf[8][Hh];
    const float* cs_p = cs_ext ? cs_ext : g_cs[p];
    int t = threadIdx.x, wid = t >> 5, lane = t & 31;
    int m = blockIdx.x*8 + wid;
    int b = m / Ss;
    int h0 = lane*8;
    __align__(16) __half hbuf[8];
    *(uint4*)hbuf = *(const uint4*)(g_preh + (size_t)m*NG2 + NG + h0);
    float4 s0 = *(const float4*)(g_svproj + b*Hh + h0);
    float4 s1 = *(const float4*)(g_svproj + b*Hh + h0 + 4);
    float4 f0 = *(const float4*)(b_fgi + h0);
    float4 f1 = *(const float4*)(b_fgi + h0 + 4);
    float sp[8] = {s0.x,s0.y,s0.z,s0.w,s1.x,s1.y,s1.z,s1.w};
    float bf[8] = {f0.x,f0.y,f0.z,f0.w,f1.x,f1.y,f1.z,f1.w};
    float e[8]; float esum = 0.f;
    #pragma unroll
    for (int j = 0; j < 8; j++){
        float x = __half2float(hbuf[j]) + sp[j] + bf[j];
        e[j] = __expf(__fdividef(1.f, 1.f + __expf(-x)));
        esum += e[j];
    }
    float inv = __fdividef(1.f, warp_sum(esum));
    const float* csr = cs_p + (size_t)m*Hh + h0;
    float4 c0 = *(const float4*)csr;
    float4 c1 = *(const float4*)(csr + 4);
    float cv[8] = {c0.x,c0.y,c0.z,c0.w,c1.x,c1.y,c1.z,c1.w};
    float4 o0, o1;
    o0.x = e[0]*inv*cv[0]; o0.y = e[1]*inv*cv[1]; o0.z = e[2]*inv*cv[2]; o0.w = e[3]*inv*cv[3];
    o1.x = e[4]*inv*cv[4]; o1.y = e[5]*inv*cv[5]; o1.z = e[6]*inv*cv[6]; o1.w = e[7]*inv*cv[7];
    *(float4*)&sbuf[wid][h0]     = o0;
    *(float4*)&sbuf[wid][h0 + 4] = o1;
    __syncthreads();
    // reduce 8 rows -> one partial per h
    float acc = sbuf[0][t] + sbuf[1][t] + sbuf[2][t] + sbuf[3][t]
              + sbuf[4][t] + sbuf[5][t] + sbuf[6][t] + sbuf[7][t];
    g_scp[(size_t)blockIdx.x*Hh + t] = acc;
}

// new_scs + new_sv from fgi block partials; 1024 threads, 16 partials per group
__global__ void __launch_bounds__(1024) k_scs(int p, int q){
    __shared__ float ps[4][Hh];
    int b = blockIdx.x, t = threadIdx.x, h = t & 255, qd = t >> 8;
    float acc = 0.f;
    #pragma unroll
    for (int j = 0; j < 16; j++)
        acc += g_scp[(size_t)(b*FBLK + qd*16 + j)*Hh + h];
    ps[qd][h] = acc;
    __syncthreads();
    if (t < 256){
        int i = b*Hh + h;
        float ns = g_fgsm[i]*g_scs[p][i] + ps[0][h]+ps[1][h]+ps[2][h]+ps[3][h];
        g_scs[q][i] = ns;
        g_sv[q][i]  = g_ogg[i] * tanhf(ns);
    }
}

// biasmat = new_sv @ W_g^T + gate_bias; grid (7, Bb), 1024 threads, K split
__global__ void __launch_bounds__(1024) k_biasmat(const float* __restrict__ gate_bias, int q){
    __shared__ float ssv[Hh];
    __shared__ float pa[4][Hh];
    int g = blockIdx.x, b = blockIdx.y, t = threadIdx.x, h = t & 255, qd = t >> 8;
    if (t < 256) ssv[h] = g_sv[q][b*Hh + h];
    __syncthreads();
    float a = 0.f;
    int k0 = qd*64;
    #pragma unroll 4
    for (int k = k0; k < k0+64; k++)
        a += ssv[k] * g_Wgt[(size_t)k*NG + g*Hh + h];
    pa[qd][h] = a;
    __syncthreads();
    if (t < 256)
        g_biasmat[(size_t)b*NG + g*Hh + h] = gate_bias[g*Hh+h] + pa[0][h]+pa[1][h]+pa[2][h]+pa[3][h];
}

// X = [hb | ha | hh | wv] -> fp16 hi, chunked pre-swizzled; 8 rows per 1024-thr block
__global__ void __launch_bounds__(1024) k_buildXs(const int* __restrict__ idx,
                                                  const float* __restrict__ embed,
                                                  const float* hh_ext, int p){
    const float* hh = hh_ext ? hh_ext : g_hh[p];
    int t = threadIdx.x;
    int m = blockIdx.x*8 + (t >> 7);
    int mtile = m >> 7, r = m & 127, s = m % Ss;
    int sc0 = (t & 127) * 8;              // 0..1023
    int chunk = sc0 >> 6, within = sc0 & 63;
    int seg = sc0 >> 8, h0 = sc0 & 255;
    float v[8];
    #pragma unroll
    for (int j = 0; j < 8; j++) v[j] = 0.f;
    auto add8 = [&](const float* pp){
        float4 a = *(const float4*)pp;
        float4 b = *(const float4*)(pp + 4);
        v[0]+=a.x; v[1]+=a.y; v[2]+=a.z; v[3]+=a.w;
        v[4]+=b.x; v[5]+=b.y; v[6]+=b.z; v[7]+=b.w;
    };
    if (seg == 0){
        if (s >= 1) add8(hh + (size_t)(m-1)*Hh + h0);
        if (s >= 2) add8(hh + (size_t)(m-2)*Hh + h0);
    } else if (seg == 1){
        if (s+1 < Ss) add8(hh + (size_t)(m+1)*Hh + h0);
        if (s+2 < Ss) add8(hh + (size_t)(m+2)*Hh + h0);
    } else if (seg == 2){
        add8(hh + (size_t)m*Hh + h0);
    } else {
        add8(embed + (size_t)idx[m]*Hh + h0);
    }
    __align__(16) __half o[8];
    #pragma unroll
    for (int j = 0; j < 8; j++) o[j] = __float2half_rn(v[j]);
    uint32_t cb = ((uint32_t)within*2) ^ ((uint32_t)(r & 7) << 4);
    char* dst = (char*)g_Xs + ((size_t)(mtile*CHK + chunk))*ABLK + (size_t)r*128 + cb;
    *(uint4*)dst = *(const uint4*)o;
}

// ---------------- bulk-copy HMMA GEMM: preh = X @ Wn^T ----------------
// persistent, tile 128x128, 4 warps of 64x64, 3-stage bulk+mbarrier, 2 CTAs/SM,
// fragment double-buffering across ks + early empty-arrive after last LDSM
__global__ void __launch_bounds__(128,2) k_mma(int cap){
    extern __shared__ char smc[];
    uint32_t sb = smem_u32(smc);
    uint32_t dbase = (sb + 1023) & ~1023u;
    uint32_t mb = dbase + NSTG*STG;
    int tid = threadIdx.x, wid = tid >> 5, lane = tid & 31;
    int wm = wid >> 1, wn = wid & 1;     // warp tile 64(M) x 64(N)

    if (tid == 0){
        #pragma unroll
        for (int s = 0; s < NSTG; s++){
            asm volatile("mbarrier.init.shared.b64 [%0], %1;" :: "r"(mb + s*8), "r"(1) : "memory");
            asm volatile("mbarrier.init.shared.b64 [%0], %1;" :: "r"(mb + 24 + s*8), "r"(4) : "memory");
        }
    }
    __syncthreads();

    uint32_t lh16 = (uint32_t)(lane >> 4) << 4;
    uint32_t lb16 = (uint32_t)((lane >> 3) & 1) << 4;
    uint32_t aPre[4], aSwm[4], bPre[4], bSwm[4];
    #pragma unroll
    for (int mi = 0; mi < 4; mi++){
        int row = wm*64 + mi*16 + (lane & 15);
        aPre[mi] = (uint32_t)row*128;
        aSwm[mi] = (uint32_t)(row & 7) << 4;
    }
    #pragma unroll
    for (int nj = 0; nj < 4; nj++){
        int row = wn*64 + nj*16 + ((lane >> 4) << 3) + (lane & 7);
        bPre[nj] = (uint32_t)row*128;
        bSwm[nj] = (uint32_t)(row & 7) << 4;
    }

    auto issue = [&](int G){
        int cc = G / CHK;
        int tl = blockIdx.x + NCTA*cc;
        if (tl >= cap) return;
        int t = G % CHK;
        int s = G % 3;
        int bm = tl >> 4, bn = tl & 15;
        const char* srcA = (const char*)g_Xs + ((size_t)(bm*CHK + t))*ABLK;
        const char* srcB = (const char*)g_Wn + ((size_t)(bn*CHK + t))*BBLK;
        uint32_t fb = mb + s*8;
        uint32_t dA = dbase + s*STG;
        uint32_t dB = dA + ABLK;
        asm volatile("mbarrier.arrive.expect_tx.shared.b64 _, [%0], %1;"
                     :: "r"(fb), "r"((uint32_t)STG) : "memory");
        asm volatile("cp.async.bulk.shared::cta.global.mbarrier::complete_tx::bytes [%0], [%1], %2, [%3];"
                     :: "r"(dA), "l"(srcA), "r"((uint32_t)ABLK), "r"(fb) : "memory");
        asm volatile("cp.async.bulk.shared::cta.global.mbarrier::complete_tx::bytes [%0], [%1], %2, [%3];"
                     :: "r"(dB), "l"(srcB), "r"((uint32_t)BBLK), "r"(fb) : "memory");
    };

    if (tid == 0){
        #pragma unroll
        for (int g = 0; g < NSTG; g++) issue(g);
    }

    int c = 0;
    for (int tile = blockIdx.x; tile < cap; tile += NCTA, c++){
        int bm = tile >> 4, bn = tile & 15;

        float acc[4][8][4];
        #pragma unroll
        for (int i = 0; i < 4; i++)
            #pragma unroll
            for (int j = 0; j < 8; j++)
                #pragma unroll
                for (int r = 0; r < 4; r++) acc[i][j][r] = 0.f;

        for (int t = 0; t < CHK; t++){
            int G = c*CHK + t;
            int s = G % 3;
            uint32_t par = (uint32_t)(G / 3) & 1u;
            mbar_wait(mb + s*8, par);

            uint32_t stA = dbase + s*STG;
            uint32_t stB = stA + ABLK;
            uint32_t afr[2][4][4], bfr[2][4][4];
            #pragma unroll
            for (int mi = 0; mi < 4; mi++)
                ldsm4(afr[0][mi], stA + aPre[mi] + (lh16 ^ aSwm[mi]));
            #pragma unroll
            for (int nj = 0; nj < 4; nj++)
                ldsm4(bfr[0][nj], stB + bPre[nj] + (lb16 ^ bSwm[nj]));

            #pragma unroll
            for (int ks = 0; ks < 4; ks++){
                int cur = ks & 1, nxt = cur ^ 1;
                if (ks < 3){
                    uint32_t ca = (uint32_t)((ks+1)*32) + lh16;
                    uint32_t cb = (uint32_t)((ks+1)*32) + lb16;
                    #pragma unroll
                    for (int mi = 0; mi < 4; mi++)
                        ldsm4(afr[nxt][mi], stA + aPre[mi] + (ca ^ aSwm[mi]));
                    #pragma unroll
                    for (int nj = 0; nj < 4; nj++)
                        ldsm4(bfr[nxt][nj], stB + bPre[nj] + (cb ^ bSwm[nj]));
                } else {
                    if (lane == 0)
                        asm volatile("mbarrier.arrive.shared.b64 _, [%0];" :: "r"(mb + 24 + s*8) : "memory");
                }
                #pragma unroll
                for (int mi = 0; mi < 4; mi++){
                    #pragma unroll
                    for (int nj = 0; nj < 4; nj++){
                        mma16816(acc[mi][2*nj],   afr[cur][mi], bfr[cur][nj][0], bfr[cur][nj][1]);
                        mma16816(acc[mi][2*nj+1], afr[cur][mi], bfr[cur][nj][2], bfr[cur][nj][3]);
                    }
                }
            }

            if (tid == 0){
                mbar_wait(mb + 24 + s*8, par);
                issue(G + NSTG);
            }
        }

        int colbase = bn*128 + wn*64;
        #pragma unroll
        for (int mi = 0; mi < 4; mi++){
            int r0 = bm*128 + wm*64 + mi*16 + (lane >> 2);
            __half* out0 = g_preh + (size_t)r0*NG2 + colbase;
            __half* out1 = g_preh + (size_t)(r0+8)*NG2 + colbase;
            #pragma unroll
            for (int nj = 0; nj < 8; nj++){
                int col = nj*8 + (lane & 3)*2;
                *(__half2*)(out0 + col) = __floats2half2_rn(acc[mi][nj][0], acc[mi][nj][1]);
                *(__half2*)(out1 + col) = __floats2half2_rn(acc[mi][nj][2], acc[mi][nj][3]);
            }
        }
    }
}

// activations + state update, warp-per-row (8 rows/block), shuffle-only reduce
__global__ void __launch_bounds__(256) k_act(const float* cs_ext, int p, int q){
    const float* cs = cs_ext ? cs_ext : g_cs[p];
    int t = threadIdx.x, wid = t >> 5, lane = t & 31;
    int m = blockIdx.x*8 + wid;
    int b = m / Ss, s = m % Ss;
    int h0 = lane*8;
    const __half* pr = g_preh + (size_t)m*NG2;
    const float* bias = g_biasmat + (size_t)b*NG;

    float eg[5][8];
    float esum = 0.f;
    #pragma unroll
    for (int g = 0; g < 5; g++){
        __align__(16) __half hb[8];
        *(uint4*)hb = *(const uint4*)(pr + g*Hh + h0);
        float4 b0 = *(const float4*)(bias + g*Hh + h0);
        float4 b1 = *(const float4*)(bias + g*Hh + h0 + 4);
        float bb[8] = {b0.x,b0.y,b0.z,b0.w,b1.x,b1.y,b1.z,b1.w};
        #pragma unroll
        for (int j = 0; j < 8; j++){
            float x = __half2float(hb[j]) + bb[j];
            float v = __fdividef(1.f, 1.f + __expf(-x));
            eg[g][j] = __expf(v);
            esum += eg[g][j];
        }
    }
    float inv = __fdividef(1.f, warp_sum(esum));

    __align__(16) __half h5[8], h6[8];
    *(uint4*)h5 = *(const uint4*)(pr + 5*Hh + h0);
    *(uint4*)h6 = *(const uint4*)(pr + 6*Hh + h0);
    float4 b50 = *(const float4*)(bias + 5*Hh + h0);
    float4 b51 = *(const float4*)(bias + 5*Hh + h0 + 4);
    float4 b60 = *(const float4*)(bias + 6*Hh + h0);
    float4 b61 = *(const float4*)(bias + 6*Hh + h0 + 4);
    float bb5[8] = {b50.x,b50.y,b50.z,b50.w,b51.x,b51.y,b51.z,b51.w};
    float bb6[8] = {b60.x,b60.y,b60.z,b60.w,b61.x,b61.y,b61.z,b61.w};

    float cbv[8], cav[8], csm[8], scsv[8];
    #pragma unroll
    for (int j = 0; j < 8; j++){ cbv[j] = 0.f; cav[j] = 0.f; }
    auto add8 = [&](float* dst, const float* pp){
        float4 a = *(const float4*)pp;
        float4 b2 = *(const float4*)(pp + 4);
        dst[0]+=a.x; dst[1]+=a.y; dst[2]+=a.z; dst[3]+=a.w;
        dst[4]+=b2.x; dst[5]+=b2.y; dst[6]+=b2.z; dst[7]+=b2.w;
    };
    if (s >= 1)   add8(cbv, cs + (size_t)(m-1)*Hh + h0);
    if (s >= 2)   add8(cbv, cs + (size_t)(m-2)*Hh + h0);
    if (s+1 < Ss) add8(cav, cs + (size_t)(m+1)*Hh + h0);
    if (s+2 < Ss) add8(cav, cs + (size_t)(m+2)*Hh + h0);
    {
        float4 a = *(const float4*)(cs + (size_t)m*Hh + h0);
        float4 b2 = *(const float4*)(cs + (size_t)m*Hh + h0 + 4);
        csm[0]=a.x; csm[1]=a.y; csm[2]=a.z; csm[3]=a.w;
        csm[4]=b2.x; csm[5]=b2.y; csm[6]=b2.z; csm[7]=b2.w;
        float4 c2 = *(const float4*)(g_scs[p] + b*Hh + h0);
        float4 d2 = *(const float4*)(g_scs[p] + b*Hh + h0 + 4);
        scsv[0]=c2.x; scsv[1]=c2.y; scsv[2]=c2.z; scsv[3]=c2.w;
        scsv[4]=d2.x; scsv[5]=d2.y; scsv[6]=d2.z; scsv[7]=d2.w;
    }
    float ncsv[8], nhhv[8];
    #pragma unroll
    for (int j = 0; j < 8; j++){
        float og = __fdividef(1.f, 1.f + __expf(-(__half2float(h5[j]) + bb5[j])));
        float u  = tanhf(__half2float(h6[j]) + bb6[j]);
        float ncs = eg[1][j]*inv*cbv[j] + eg[3][j]*inv*csm[j] + eg[2][j]*inv*cav[j]
                  + eg[4][j]*inv*scsv[j] + eg[0][j]*inv*u;
        ncsv[j] = ncs;
        nhhv[j] = og * tanhf(ncs);
    }
    float* dc = g_cs[q] + (size_t)m*Hh + h0;
    float* dh = g_hh[q] + (size_t)m*Hh + h0;
    *(float4*)dc     = make_float4(ncsv[0],ncsv[1],ncsv[2],ncsv[3]);
    *(float4*)(dc+4) = make_float4(ncsv[4],ncsv[5],ncsv[6],ncsv[7]);
    *(float4*)dh     = make_float4(nhhv[0],nhhv[1],nhhv[2],nhhv[3]);
    *(float4*)(dh+4) = make_float4(nhhv[4],nhhv[5],nhhv[6],nhhv[7]);
}

// output head; 1024 threads, K split
__global__ void __launch_bounds__(1024) k_head(const float* __restrict__ b1,
                       const float* __restrict__ Wout, const float* __restrict__ bout,
                       int p, float* __restrict__ out, int out_size){
    __shared__ float sa[Hh], ssv[Hh], conc[Hh], fc[5];
    __shared__ float pc[4][Hh];
    __shared__ float lse;
    int b = blockIdx.x, t = threadIdx.x, h = t & 255, qd = t >> 8;
    const float* hh = g_hh[p];
    float av = 0.f;
    for (int s2 = 0; s2 < 128; s2++) av += hh[(size_t)(b*Ss + qd*128 + s2)*Hh + h];
    pc[qd][h] = av;
    if (t < 256) ssv[h] = g_sv[p][b*Hh + h];
    __syncthreads();
    if (t < 256) sa[h] = (pc[0][h]+pc[1][h]+pc[2][h]+pc[3][h]) * (1.f/Ss);
    __syncthreads();
    float c = 0.f;
    int k0 = qd*128;
    #pragma unroll 4
    for (int k2 = 0; k2 < 128; k2++){
        int kk = k0 + k2;
        float src = (kk < 256) ? sa[kk] : ssv[kk-256];
        c += src * g_W1t[kk*Hh + h];
    }
    pc[qd][h] = c;
    __syncthreads();
    if (t < 256) conc[h] = b1[h] + pc[0][h]+pc[1][h]+pc[2][h]+pc[3][h];
    __syncthreads();
    if (t < 5){
        float f = bout[t];
        const float* wo = Wout + (size_t)t*Hh;
        for (int k = 0; k < Hh; k++) f += conc[k]*wo[k];
        fc[t] = f;
    }
    __syncthreads();
    if (t == 0){
        float mx = fc[0];
        #pragma unroll
        for (int i = 1; i < 5; i++) mx = fmaxf(mx, fc[i]);
        float sum = 0.f;
        #pragma unroll
        for (int i = 0; i < 5; i++) sum += expf(fc[i] - mx);
        lse = mx + logf(sum);
    }
    __syncthreads();
    if (t < 5 && out_size >= Bb*5) out[b*5 + t] = fc[t] - lse;
    if (t < 256 && out_size >= Bb*5 + Bb*Hh) out[Bb*5 + b*Hh + h] = ssv[h];
}

// ---------------- host ----------------
extern "C" void kernel_launch(void* const* d_in, const int* in_sizes, int n_in,
                              void* d_out, int out_size){
    const int*   idx       = (const int*)  d_in[0];
    const float* hh0       = (const float*)d_in[2];
    const float* cs0       = (const float*)d_in[3];
    const float* embed     = (const float*)d_in[4];
    const float* W_lr      = (const float*)d_in[5];
    const float* W_c       = (const float*)d_in[6];
    const float* W_x       = (const float*)d_in[7];
    const float* W_g       = (const float*)d_in[8];
    const float* gate_bias = (const float*)d_in[9];
    const float* W_fg_g    = (const float*)d_in[10];
    const float* W_fg_h    = (const float*)d_in[11];
    const float* W_fgi_g   = (const float*)d_in[12];
    const float* W_fgi_h   = (const float*)d_in[13];
    const float* W_og_g    = (const float*)d_in[14];
    const float* W_og_h    = (const float*)d_in[15];
    const float* b_fg      = (const float*)d_in[16];
    const float* b_fgi     = (const float*)d_in[17];
    const float* W1        = (const float*)d_in[18];
    const float* b1        = (const float*)d_in[19];
    const float* Wout      = (const float*)d_in[20];
    const float* bout      = (const float*)d_in[21];
    float* out = (float*)d_out;

    static float* wgt_ptr = nullptr;
    float* d_Wgt; cudaGetSymbolAddress((void**)&d_Wgt, g_Wgt);
    float* d_W1t; cudaGetSymbolAddress((void**)&d_W1t, g_W1t);
    (void)wgt_ptr;

    cudaFuncSetAttribute(k_mma, cudaFuncAttributeMaxDynamicSharedMemorySize, SMEM_MMA);

    k_wsplit<<<NG2, 128>>>(W_lr, W_c, W_x, W_fgi_h);
    k_tpose<<<dim3(8, 56), dim3(32, 8)>>>(W_g, d_Wgt, NG, Hh);     // W_g [1792x256] -> [256x1792]
    k_wsmt<<<dim3(8, 8, 5), dim3(32, 8)>>>(W_fg_g, W_fg_h, W_og_g, W_og_h, W_fgi_g);
    k_tpose<<<dim3(16, 8), dim3(32, 8)>>>(W1, d_W1t, Hh, 512);     // W1 [256x512] -> [512x256]

    int p = 0;
    for (int layer = 0; layer < 2; layer++){
        int q = 1 - p;
        const float* hh_ext = (layer == 0) ? hh0 : nullptr;
        const float* cs_ext = (layer == 0) ? cs0 : nullptr;
        k_buildXs<<<BS/8, 1024>>>(idx, embed, hh_ext, p);
        k_small<<<Bb, 1024>>>(b_fg, gate_bias, hh_ext, cs_ext, p);
        k_mma<<<NCTA, 128, SMEM_MMA>>>(NTILE);
        k_fgi<<<BS/8, 256>>>(b_fgi, cs_ext, p);
        k_scs<<<Bb, 1024>>>(p, q);
        k_biasmat<<<dim3(7, Bb), 1024>>>(gate_bias, q);
        k_act<<<BS/8, 256>>>(cs_ext, p, q);
        p = q;
    }
    k_head<<<Bb, 1024>>>(b1, Wout, bout, p, out, out_size);
}

// round 16
// speedup vs baseline: 1.2274x; 1.0053x over previous
#include <cuda_runtime.h>
#include <cuda_fp16.h>
#include <math.h>
#include <stdint.h>

#define Bb 32
#define Ss 512
#define Hh 256
#define BS (Bb*Ss)          // 16384 rows
#define NG 1792             // 7 gates * 256 (biasmat width)
#define NG2 2048            // GEMM N: 7 gates + fgi projection
#define CHK 16              // K chunks (64 cols) : K = 1024, fp16 hi only
#define ABLK (128*128)      // A chunk block bytes = 16KB
#define BBLK (128*128)      // B chunk block bytes = 16KB
#define NSTG 3
#define STG (ABLK + BBLK)   // 32KB
#define SMEM_MMA (1024 + NSTG*STG + 64)
#define NTILE 2048          // 16 (n) x 128 (m)
#define NCTA 296
#define FBLK 64             // fgi partial blocks per batch (512/8)

// ---------------- scratch (device globals; no allocation allowed) ----------------
__device__ float g_hh[2][BS*Hh];
__device__ float g_cs[2][BS*Hh];
__device__ float g_sv[2][Bb*Hh];
__device__ float g_scs[2][Bb*Hh];
__device__ float g_fgsm[Bb*Hh];
__device__ float g_ogg[Bb*Hh];
__device__ float g_svproj[Bb*Hh];
__device__ float g_biasmat[Bb*NG];
__device__ __half g_preh[(size_t)BS*NG2];     // fp16 pre-activations (67MB)
__device__ float g_scp[(BS/8)*Hh];            // fgi block partial sums (2MB)
__device__ float g_Wgt[Hh*NG];                // W_g transposed  [k][g*256+h]
__device__ float g_WsmT[5][Hh*Hh];            // transposed small gates
__device__ float g_W1t[512*Hh];               // W1^T [k][h]
// A: [128 mtiles][16 chunks][128 rows][64 cols] fp16 hi, pre-swizzled (32MB)
__device__ __align__(256) __half g_Xs[(size_t)128*16*128*64];
// B: [16 ntiles][16 chunks][128 rows][64 cols] fp16 hi, pre-swizzled (4MB, L2-resident)
__device__ __align__(256) __half g_Wn[(size_t)16*16*128*64];

__device__ __forceinline__ float sigmoidf(float x){ return 1.f/(1.f+expf(-x)); }

__device__ __forceinline__ uint32_t smem_u32(const void* p){
    uint32_t a;
    asm("{ .reg .u64 t; cvta.to.shared.u64 t, %1; cvt.u32.u64 %0, t; }" : "=r"(a) : "l"(p));
    return a;
}

__device__ __forceinline__ void ldsm4(uint32_t (&r)[4], uint32_t a){
    asm volatile("ldmatrix.sync.aligned.m8n8.x4.shared.b16 {%0,%1,%2,%3}, [%4];"
        : "=r"(r[0]), "=r"(r[1]), "=r"(r[2]), "=r"(r[3]) : "r"(a));
}

__device__ __forceinline__ void mma16816(float (&c)[4], const uint32_t (&a)[4],
                                         uint32_t b0, uint32_t b1){
    asm volatile("mma.sync.aligned.m16n8k16.row.col.f32.f16.f16.f32 "
        "{%0,%1,%2,%3}, {%4,%5,%6,%7}, {%8,%9}, {%0,%1,%2,%3};"
        : "+f"(c[0]), "+f"(c[1]), "+f"(c[2]), "+f"(c[3])
        : "r"(a[0]), "r"(a[1]), "r"(a[2]), "r"(a[3]), "r"(b0), "r"(b1));
}

__device__ __forceinline__ void mbar_wait(uint32_t mbar, uint32_t parity){
    uint32_t done;
    asm volatile("{\n\t.reg .pred p;\n\tmbarrier.try_wait.parity.acquire.cta.shared::cta.b64 p, [%1], %2;\n\tselp.b32 %0, 1, 0, p;\n\t}"
        : "=r"(done) : "r"(mbar), "r"(parity) : "memory");
    while (!done){
        asm volatile("{\n\t.reg .pred p;\n\tmbarrier.try_wait.parity.acquire.cta.shared::cta.b64 p, [%1], %2, 0x989680;\n\tselp.b32 %0, 1, 0, p;\n\t}"
            : "=r"(done) : "r"(mbar), "r"(parity) : "memory");
    }
}

__device__ __forceinline__ float warp_sum(float v){
    #pragma unroll
    for (int o = 16; o > 0; o >>= 1) v += __shfl_xor_sync(0xffffffffu, v, o);
    return v;
}

// ---------------- setup kernels ----------------
// W rows -> fp16, chunked pre-swizzled; n in [1792,2048) = fgi projection columns
__global__ void k_wsplit(const float* __restrict__ W_lr, const float* __restrict__ W_c,
                         const float* __restrict__ W_x, const float* __restrict__ W_fgi_h){
    int n = blockIdx.x;            // 0..2047
    int ntile = n >> 7, r = n & 127;
    int k0 = threadIdx.x * 8;      // 128 threads
    float4 a = make_float4(0.f,0.f,0.f,0.f), b = a;
    if (n < NG){
        int g = n >> 8, h = n & 255;
        const float* src;
        if (k0 < 512)      src = W_lr + ((size_t)g*Hh + h)*512 + k0;
        else if (k0 < 768) src = W_c  + ((size_t)g*Hh + h)*Hh + (k0-512);
        else               src = W_x  + ((size_t)g*Hh + h)*Hh + (k0-768);
        a = *(const float4*)src;
        b = *(const float4*)(src + 4);
    } else if (k0 >= 512 && k0 < 768){
        int h = n - NG;
        const float* src = W_fgi_h + (size_t)h*Hh + (k0-512);
        a = *(const float4*)src;
        b = *(const float4*)(src + 4);
    }
    __align__(16) __half o[8];
    o[0]=__float2half_rn(a.x); o[1]=__float2half_rn(a.y);
    o[2]=__float2half_rn(a.z); o[3]=__float2half_rn(a.w);
    o[4]=__float2half_rn(b.x); o[5]=__float2half_rn(b.y);
    o[6]=__float2half_rn(b.z); o[7]=__float2half_rn(b.w);
    int chunk = k0 >> 6, within = k0 & 63;
    uint32_t cb = ((uint32_t)within*2) ^ ((uint32_t)(r & 7) << 4);
    char* dst = (char*)g_Wn + ((size_t)(ntile*CHK + chunk))*BBLK + (size_t)r*128 + cb;
    *(uint4*)dst = *(const uint4*)o;
}

// tiled transpose: in [R][C] -> out [C][R]; grid(C/32, R/32), block(32,8)
__global__ void k_tpose(const float* __restrict__ in, float* __restrict__ out, int R, int C){
    __shared__ float tile[32][33];
    int c0 = blockIdx.x*32, r0 = blockIdx.y*32;
    int tx = threadIdx.x, ty = threadIdx.y;
    #pragma unroll
    for (int i = 0; i < 32; i += 8)
        tile[ty+i][tx] = in[(size_t)(r0+ty+i)*C + c0+tx];
    __syncthreads();
    #pragma unroll
    for (int i = 0; i < 32; i += 8)
        out[(size_t)(c0+ty+i)*R + r0+tx] = tile[tx][ty+i];
}

// 5 small gate matrices 256x256, transposed; grid(8,8,5), block(32,8)
__global__ void k_wsmt(const float* __restrict__ W_fg_g, const float* __restrict__ W_fg_h,
                       const float* __restrict__ W_og_g, const float* __restrict__ W_og_h,
                       const float* __restrict__ W_fgi_g){
    __shared__ float tile[32][33];
    int which = blockIdx.z;
    const float* in = (which == 0) ? W_fg_g : (which == 1) ? W_fg_h :
                      (which == 2) ? W_og_g : (which == 3) ? W_og_h : W_fgi_g;
    float* out = g_WsmT[which];
    int c0 = blockIdx.x*32, r0 = blockIdx.y*32;
    int tx = threadIdx.x, ty = threadIdx.y;
    #pragma unroll
    for (int i = 0; i < 32; i += 8)
        tile[ty+i][tx] = in[(size_t)(r0+ty+i)*Hh + c0+tx];
    __syncthreads();
    #pragma unroll
    for (int i = 0; i < 32; i += 8)
        out[(size_t)(c0+ty+i)*Hh + r0+tx] = tile[tx][ty+i];
}

// ---------------- per-layer kernels ----------------
// small sentence gates; 1024 threads, K split; layer0 computes avgs from hh0/cs0
__global__ void __launch_bounds__(1024) k_small(const float* __restrict__ b_fg,
                        const float* __restrict__ gate_bias,
                        const float* hh_ext, const float* cs_ext, int p){
    __shared__ float ssv[Hh], sav[Hh];
    __shared__ float pf[4][Hh], po[4][Hh], psp[4][Hh];
    __shared__ float red[32];
    int b = blockIdx.x, t = threadIdx.x, h = t & 255, qd = t >> 8;
    const float* hh = hh_ext ? hh_ext : g_hh[p];
    float av = 0.f;
    for (int s2 = 0; s2 < 128; s2++) av += hh[(size_t)(b*Ss + qd*128 + s2)*Hh + h];
    pf[qd][h] = av;
    if (cs_ext){
        float cv = 0.f;
        for (int s2 = 0; s2 < 128; s2++) cv += cs_ext[(size_t)(b*Ss + qd*128 + s2)*Hh + h];
        po[qd][h] = cv;
    } else {
        if (t < 256) ssv[h] = g_sv[p][b*Hh+h];
    }
    __syncthreads();
    if (t < 256){
        sav[h] = (pf[0][h]+pf[1][h]+pf[2][h]+pf[3][h]) * (1.f/Ss);
        if (cs_ext){
            g_scs[p][b*Hh+h] = (po[0][h]+po[1][h]+po[2][h]+po[3][h]) * (1.f/Ss);
            ssv[h] = sav[h];                          // sv0 = avg(hh0)
        }
    }
    __syncthreads();
    float f = 0.f, o = 0.f, sp = 0.f;
    int k0 = qd*64;
    #pragma unroll 4
    for (int k = k0; k < k0+64; k++){
        float s = ssv[k], a = sav[k];
        int off = k*Hh + h;
        f  += s*g_WsmT[0][off] + a*g_WsmT[1][off];
        o  += s*g_WsmT[2][off] + a*g_WsmT[3][off];
        sp += s*g_WsmT[4][off];
    }
    pf[qd][h] = f; po[qd][h] = o; psp[qd][h] = sp;
    __syncthreads();
    float e = 0.f;
    if (t < 256){
        f  = pf[0][h]+pf[1][h]+pf[2][h]+pf[3][h] + b_fg[h];
        o  = po[0][h]+po[1][h]+po[2][h]+po[3][h] + gate_bias[5*Hh + h];
        sp = psp[0][h]+psp[1][h]+psp[2][h]+psp[3][h];
        f = sigmoidf(f);
        g_ogg[b*Hh+h]    = sigmoidf(o);
        g_svproj[b*Hh+h] = sp;
        e = expf(f);
    }
    int lane = t & 31, w = t >> 5;
    float r = warp_sum(e);
    if (lane == 0) red[w] = r;
    __syncthreads();
    if (t < 32){
        float rr = red[t];
        #pragma unroll
        for (int o2 = 16; o2 > 0; o2 >>= 1) rr += __shfl_xor_sync(0xffffffffu, rr, o2);
        if (t == 0) red[0] = rr;
    }
    __syncthreads();
    if (t < 256) g_fgsm[b*Hh+h] = e / red[0];
}

// fgi softmax, warp-per-row (8 rows/block); emits block-partial sum of scores*cs
__global__ void __launch_bounds__(256) k_fgi(const float* __restrict__ b_fgi,
                                             const float* cs_ext, int p){
    __shared__ float sbuf[8][Hh];
    const float* cs_p = cs_ext ? cs_ext : g_cs[p];
    int t = threadIdx.x, wid = t >> 5, lane = t & 31;
    int m = blockIdx.x*8 + wid;
    int b = m / Ss;
    int h0 = lane*8;
    __align__(16) __half hbuf[8];
    *(uint4*)hbuf = *(const uint4*)(g_preh + (size_t)m*NG2 + NG + h0);
    float4 s0 = *(const float4*)(g_svproj + b*Hh + h0);
    float4 s1 = *(const float4*)(g_svproj + b*Hh + h0 + 4);
    float4 f0 = *(const float4*)(b_fgi + h0);
    float4 f1 = *(const float4*)(b_fgi + h0 + 4);
    float sp[8] = {s0.x,s0.y,s0.z,s0.w,s1.x,s1.y,s1.z,s1.w};
    float bf[8] = {f0.x,f0.y,f0.z,f0.w,f1.x,f1.y,f1.z,f1.w};
    float e[8]; float esum = 0.f;
    #pragma unroll
    for (int j = 0; j < 8; j++){
        float x = __half2float(hbuf[j]) + sp[j] + bf[j];
        e[j] = __expf(__fdividef(1.f, 1.f + __expf(-x)));
        esum += e[j];
    }
    float inv = __fdividef(1.f, warp_sum(esum));
    const float* csr = cs_p + (size_t)m*Hh + h0;
    float4 c0 = *(const float4*)csr;
    float4 c1 = *(const float4*)(csr + 4);
    float cv[8] = {c0.x,c0.y,c0.z,c0.w,c1.x,c1.y,c1.z,c1.w};
    float4 o0, o1;
    o0.x = e[0]*inv*cv[0]; o0.y = e[1]*inv*cv[1]; o0.z = e[2]*inv*cv[2]; o0.w = e[3]*inv*cv[3];
    o1.x = e[4]*inv*cv[4]; o1.y = e[5]*inv*cv[5]; o1.z = e[6]*inv*cv[6]; o1.w = e[7]*inv*cv[7];
    *(float4*)&sbuf[wid][h0]     = o0;
    *(float4*)&sbuf[wid][h0 + 4] = o1;
    __syncthreads();
    float acc = sbuf[0][t] + sbuf[1][t] + sbuf[2][t] + sbuf[3][t]
              + sbuf[4][t] + sbuf[5][t] + sbuf[6][t] + sbuf[7][t];
    g_scp[(size_t)blockIdx.x*Hh + t] = acc;
}

// merged: new_scs/new_sv (recomputed per block; g==0 persists) + biasmat column g
// grid (7, Bb), 1024 threads
__global__ void __launch_bounds__(1024) k_scsbias(const float* __restrict__ gate_bias,
                                                  int p, int q){
    __shared__ float ps[4][Hh];
    __shared__ float ssv[Hh];
    __shared__ float pa[4][Hh];
    int g = blockIdx.x, b = blockIdx.y, t = threadIdx.x, h = t & 255, qd = t >> 8;
    float acc = 0.f;
    #pragma unroll
    for (int j = 0; j < 16; j++)
        acc += g_scp[(size_t)(b*FBLK + qd*16 + j)*Hh + h];
    ps[qd][h] = acc;
    __syncthreads();
    if (t < 256){
        int i = b*Hh + h;
        float ns = g_fgsm[i]*g_scs[p][i] + ps[0][h]+ps[1][h]+ps[2][h]+ps[3][h];
        float nsv = g_ogg[i] * tanhf(ns);
        ssv[h] = nsv;
        if (g == 0){ g_scs[q][i] = ns; g_sv[q][i] = nsv; }
    }
    __syncthreads();
    float a = 0.f;
    int k0 = qd*64;
    #pragma unroll 4
    for (int k = k0; k < k0+64; k++)
        a += ssv[k] * g_Wgt[(size_t)k*NG + g*Hh + h];
    pa[qd][h] = a;
    __syncthreads();
    if (t < 256)
        g_biasmat[(size_t)b*NG + g*Hh + h] = gate_bias[g*Hh+h] + pa[0][h]+pa[1][h]+pa[2][h]+pa[3][h];
}

// X = [hb | ha | hh | wv] -> fp16 hi, chunked pre-swizzled; 8 rows per 1024-thr block
__global__ void __launch_bounds__(1024) k_buildXs(const int* __restrict__ idx,
                                                  const float* __restrict__ embed,
                                                  const float* hh_ext, int p){
    const float* hh = hh_ext ? hh_ext : g_hh[p];
    int t = threadIdx.x;
    int m = blockIdx.x*8 + (t >> 7);
    int mtile = m >> 7, r = m & 127, s = m % Ss;
    int sc0 = (t & 127) * 8;              // 0..1023
    int chunk = sc0 >> 6, within = sc0 & 63;
    int seg = sc0 >> 8, h0 = sc0 & 255;
    float v[8];
    #pragma unroll
    for (int j = 0; j < 8; j++) v[j] = 0.f;
    auto add8 = [&](const float* pp){
        float4 a = *(const float4*)pp;
        float4 b = *(const float4*)(pp + 4);
        v[0]+=a.x; v[1]+=a.y; v[2]+=a.z; v[3]+=a.w;
        v[4]+=b.x; v[5]+=b.y; v[6]+=b.z; v[7]+=b.w;
    };
    if (seg == 0){
        if (s >= 1) add8(hh + (size_t)(m-1)*Hh + h0);
        if (s >= 2) add8(hh + (size_t)(m-2)*Hh + h0);
    } else if (seg == 1){
        if (s+1 < Ss) add8(hh + (size_t)(m+1)*Hh + h0);
        if (s+2 < Ss) add8(hh + (size_t)(m+2)*Hh + h0);
    } else if (seg == 2){
        add8(hh + (size_t)m*Hh + h0);
    } else {
        add8(embed + (size_t)idx[m]*Hh + h0);
    }
    __align__(16) __half o[8];
    #pragma unroll
    for (int j = 0; j < 8; j++) o[j] = __float2half_rn(v[j]);
    uint32_t cb = ((uint32_t)within*2) ^ ((uint32_t)(r & 7) << 4);
    char* dst = (char*)g_Xs + ((size_t)(mtile*CHK + chunk))*ABLK + (size_t)r*128 + cb;
    *(uint4*)dst = *(const uint4*)o;
}

// ---------------- bulk-copy HMMA GEMM: preh = X @ Wn^T ----------------
// persistent, tile 128x128, 4 warps of 64x64, 3-stage bulk+mbarrier, 2 CTAs/SM,
// fragment double-buffering across ks + early empty-arrive after last LDSM
__global__ void __launch_bounds__(128,2) k_mma(int cap){
    extern __shared__ char smc[];
    uint32_t sb = smem_u32(smc);
    uint32_t dbase = (sb + 1023) & ~1023u;
    uint32_t mb = dbase + NSTG*STG;
    int tid = threadIdx.x, wid = tid >> 5, lane = tid & 31;
    int wm = wid >> 1, wn = wid & 1;     // warp tile 64(M) x 64(N)

    if (tid == 0){
        #pragma unroll
        for (int s = 0; s < NSTG; s++){
            asm volatile("mbarrier.init.shared.b64 [%0], %1;" :: "r"(mb + s*8), "r"(1) : "memory");
            asm volatile("mbarrier.init.shared.b64 [%0], %1;" :: "r"(mb + 24 + s*8), "r"(4) : "memory");
        }
    }
    __syncthreads();

    uint32_t lh16 = (uint32_t)(lane >> 4) << 4;
    uint32_t lb16 = (uint32_t)((lane >> 3) & 1) << 4;
    uint32_t aPre[4], aSwm[4], bPre[4], bSwm[4];
    #pragma unroll
    for (int mi = 0; mi < 4; mi++){
        int row = wm*64 + mi*16 + (lane & 15);
        aPre[mi] = (uint32_t)row*128;
        aSwm[mi] = (uint32_t)(row & 7) << 4;
    }
    #pragma unroll
    for (int nj = 0; nj < 4; nj++){
        int row = wn*64 + nj*16 + ((lane >> 4) << 3) + (lane & 7);
        bPre[nj] = (uint32_t)row*128;
        bSwm[nj] = (uint32_t)(row & 7) << 4;
    }

    auto issue = [&](int G){
        int cc = G / CHK;
        int tl = blockIdx.x + NCTA*cc;
        if (tl >= cap) return;
        int t = G % CHK;
        int s = G % 3;
        int bm = tl >> 4, bn = tl & 15;
        const char* srcA = (const char*)g_Xs + ((size_t)(bm*CHK + t))*ABLK;
        const char* srcB = (const char*)g_Wn + ((size_t)(bn*CHK + t))*BBLK;
        uint32_t fb = mb + s*8;
        uint32_t dA = dbase + s*STG;
        uint32_t dB = dA + ABLK;
        asm volatile("mbarrier.arrive.expect_tx.shared.b64 _, [%0], %1;"
                     :: "r"(fb), "r"((uint32_t)STG) : "memory");
        asm volatile("cp.async.bulk.shared::cta.global.mbarrier::complete_tx::bytes [%0], [%1], %2, [%3];"
                     :: "r"(dA), "l"(srcA), "r"((uint32_t)ABLK), "r"(fb) : "memory");
        asm volatile("cp.async.bulk.shared::cta.global.mbarrier::complete_tx::bytes [%0], [%1], %2, [%3];"
                     :: "r"(dB), "l"(srcB), "r"((uint32_t)BBLK), "r"(fb) : "memory");
    };

    if (tid == 0){
        #pragma unroll
        for (int g = 0; g < NSTG; g++) issue(g);
    }

    int c = 0;
    for (int tile = blockIdx.x; tile < cap; tile += NCTA, c++){
        int bm = tile >> 4, bn = tile & 15;

        float acc[4][8][4];
        #pragma unroll
        for (int i = 0; i < 4; i++)
            #pragma unroll
            for (int j = 0; j < 8; j++)
                #pragma unroll
                for (int r = 0; r < 4; r++) acc[i][j][r] = 0.f;

        for (int t = 0; t < CHK; t++){
            int G = c*CHK + t;
            int s = G % 3;
            uint32_t par = (uint32_t)(G / 3) & 1u;
            mbar_wait(mb + s*8, par);

            uint32_t stA = dbase + s*STG;
            uint32_t stB = stA + ABLK;
            uint32_t afr[2][4][4], bfr[2][4][4];
            #pragma unroll
            for (int mi = 0; mi < 4; mi++)
                ldsm4(afr[0][mi], stA + aPre[mi] + (lh16 ^ aSwm[mi]));
            #pragma unroll
            for (int nj = 0; nj < 4; nj++)
                ldsm4(bfr[0][nj], stB + bPre[nj] + (lb16 ^ bSwm[nj]));

            #pragma unroll
            for (int ks = 0; ks < 4; ks++){
                int cur = ks & 1, nxt = cur ^ 1;
                if (ks < 3){
                    uint32_t ca = (uint32_t)((ks+1)*32) + lh16;
                    uint32_t cb = (uint32_t)((ks+1)*32) + lb16;
                    #pragma unroll
                    for (int mi = 0; mi < 4; mi++)
                        ldsm4(afr[nxt][mi], stA + aPre[mi] + (ca ^ aSwm[mi]));
                    #pragma unroll
                    for (int nj = 0; nj < 4; nj++)
                        ldsm4(bfr[nxt][nj], stB + bPre[nj] + (cb ^ bSwm[nj]));
                } else {
                    if (lane == 0)
                        asm volatile("mbarrier.arrive.shared.b64 _, [%0];" :: "r"(mb + 24 + s*8) : "memory");
                }
                #pragma unroll
                for (int mi = 0; mi < 4; mi++){
                    #pragma unroll
                    for (int nj = 0; nj < 4; nj++){
                        mma16816(acc[mi][2*nj],   afr[cur][mi], bfr[cur][nj][0], bfr[cur][nj][1]);
                        mma16816(acc[mi][2*nj+1], afr[cur][mi], bfr[cur][nj][2], bfr[cur][nj][3]);
                    }
                }
            }

            if (tid == 0){
                mbar_wait(mb + 24 + s*8, par);
                issue(G + NSTG);
            }
        }

        int colbase = bn*128 + wn*64;
        #pragma unroll
        for (int mi = 0; mi < 4; mi++){
            int r0 = bm*128 + wm*64 + mi*16 + (lane >> 2);
            __half* out0 = g_preh + (size_t)r0*NG2 + colbase;
            __half* out1 = g_preh + (size_t)(r0+8)*NG2 + colbase;
            #pragma unroll
            for (int nj = 0; nj < 8; nj++){
                int col = nj*8 + (lane & 3)*2;
                *(__half2*)(out0 + col) = __floats2half2_rn(acc[mi][nj][0], acc[mi][nj][1]);
                *(__half2*)(out1 + col) = __floats2half2_rn(acc[mi][nj][2], acc[mi][nj][3]);
            }
        }
    }
}

// activations + state update, warp-per-row (8 rows/block); cs rows staged in smem
__global__ void __launch_bounds__(256) k_act(const float* cs_ext, int p, int q){
    __shared__ float cs_sh[12][Hh];
    const float* cs = cs_ext ? cs_ext : g_cs[p];
    int t = threadIdx.x, wid = t >> 5, lane = t & 31;
    int m0 = blockIdx.x*8;
    int s0 = m0 % Ss;
    // stage rows m0-2 .. m0+9 (zero-filled outside the sequence)
    #pragma unroll
    for (int j = 0; j < 12; j++){
        int sj = s0 - 2 + j;
        float v = 0.f;
        if (sj >= 0 && sj < Ss) v = cs[(size_t)(m0 - 2 + j)*Hh + t];
        cs_sh[j][t] = v;
    }
    __syncthreads();

    int m = m0 + wid;
    int b = m / Ss;
    int h0 = lane*8;
    int lw = wid + 2;
    const __half* pr = g_preh + (size_t)m*NG2;
    const float* bias = g_biasmat + (size_t)b*NG;

    float eg[5][8];
    float esum = 0.f;
    #pragma unroll
    for (int g = 0; g < 5; g++){
        __align__(16) __half hb[8];
        *(uint4*)hb = *(const uint4*)(pr + g*Hh + h0);
        float4 b0 = *(const float4*)(bias + g*Hh + h0);
        float4 b1 = *(const float4*)(bias + g*Hh + h0 + 4);
        float bb[8] = {b0.x,b0.y,b0.z,b0.w,b1.x,b1.y,b1.z,b1.w};
        #pragma unroll
        for (int j = 0; j < 8; j++){
            float x = __half2float(hb[j]) + bb[j];
            float v = __fdividef(1.f, 1.f + __expf(-x));
            eg[g][j] = __expf(v);
            esum += eg[g][j];
        }
    }
    float inv = __fdividef(1.f, warp_sum(esum));

    __align__(16) __half h5[8], h6[8];
    *(uint4*)h5 = *(const uint4*)(pr + 5*Hh + h0);
    *(uint4*)h6 = *(const uint4*)(pr + 6*Hh + h0);
    float4 b50 = *(const float4*)(bias + 5*Hh + h0);
    float4 b51 = *(const float4*)(bias + 5*Hh + h0 + 4);
    float4 b60 = *(const float4*)(bias + 6*Hh + h0);
    float4 b61 = *(const float4*)(bias + 6*Hh + h0 + 4);
    float bb5[8] = {b50.x,b50.y,b50.z,b50.w,b51.x,b51.y,b51.z,b51.w};
    float bb6[8] = {b60.x,b60.y,b60.z,b60.w,b61.x,b61.y,b61.z,b61.w};

    float scsv[8];
    {
        float4 c2 = *(const float4*)(g_scs[p] + b*Hh + h0);
        float4 d2 = *(const float4*)(g_scs[p] + b*Hh + h0 + 4);
        scsv[0]=c2.x; scsv[1]=c2.y; scsv[2]=c2.z; scsv[3]=c2.w;
        scsv[4]=d2.x; scsv[5]=d2.y; scsv[6]=d2.z; scsv[7]=d2.w;
    }
    float ncsv[8], nhhv[8];
    #pragma unroll
    for (int j = 0; j < 8; j++){
        float cbv = cs_sh[lw-1][h0+j] + cs_sh[lw-2][h0+j];
        float cav = cs_sh[lw+1][h0+j] + cs_sh[lw+2][h0+j];
        float csm = cs_sh[lw][h0+j];
        float og = __fdividef(1.f, 1.f + __expf(-(__half2float(h5[j]) + bb5[j])));
        float u  = tanhf(__half2float(h6[j]) + bb6[j]);
        float ncs = eg[1][j]*inv*cbv + eg[3][j]*inv*csm + eg[2][j]*inv*cav
                  + eg[4][j]*inv*scsv[j] + eg[0][j]*inv*u;
        ncsv[j] = ncs;
        nhhv[j] = og * tanhf(ncs);
    }
    float* dc = g_cs[q] + (size_t)m*Hh + h0;
    float* dh = g_hh[q] + (size_t)m*Hh + h0;
    *(float4*)dc     = make_float4(ncsv[0],ncsv[1],ncsv[2],ncsv[3]);
    *(float4*)(dc+4) = make_float4(ncsv[4],ncsv[5],ncsv[6],ncsv[7]);
    *(float4*)dh     = make_float4(nhhv[0],nhhv[1],nhhv[2],nhhv[3]);
    *(float4*)(dh+4) = make_float4(nhhv[4],nhhv[5],nhhv[6],nhhv[7]);
}

// output head; 1024 threads, K split
__global__ void __launch_bounds__(1024) k_head(const float* __restrict__ b1,
                       const float* __restrict__ Wout, const float* __restrict__ bout,
                       int p, float* __restrict__ out, int out_size){
    __shared__ float sa[Hh], ssv[Hh], conc[Hh], fc[5];
    __shared__ float pc[4][Hh];
    __shared__ float lse;
    int b = blockIdx.x, t = threadIdx.x, h = t & 255, qd = t >> 8;
    const float* hh = g_hh[p];
    float av = 0.f;
    for (int s2 = 0; s2 < 128; s2++) av += hh[(size_t)(b*Ss + qd*128 + s2)*Hh + h];
    pc[qd][h] = av;
    if (t < 256) ssv[h] = g_sv[p][b*Hh + h];
    __syncthreads();
    if (t < 256) sa[h] = (pc[0][h]+pc[1][h]+pc[2][h]+pc[3][h]) * (1.f/Ss);
    __syncthreads();
    float c = 0.f;
    int k0 = qd*128;
    #pragma unroll 4
    for (int k2 = 0; k2 < 128; k2++){
        int kk = k0 + k2;
        float src = (kk < 256) ? sa[kk] : ssv[kk-256];
        c += src * g_W1t[kk*Hh + h];
    }
    pc[qd][h] = c;
    __syncthreads();
    if (t < 256) conc[h] = b1[h] + pc[0][h]+pc[1][h]+pc[2][h]+pc[3][h];
    __syncthreads();
    if (t < 5){
        float f = bout[t];
        const float* wo = Wout + (size_t)t*Hh;
        for (int k = 0; k < Hh; k++) f += conc[k]*wo[k];
        fc[t] = f;
    }
    __syncthreads();
    if (t == 0){
        float mx = fc[0];
        #pragma unroll
        for (int i = 1; i < 5; i++) mx = fmaxf(mx, fc[i]);
        float sum = 0.f;
        #pragma unroll
        for (int i = 0; i < 5; i++) sum += expf(fc[i] - mx);
        lse = mx + logf(sum);
    }
    __syncthreads();
    if (t < 5 && out_size >= Bb*5) out[b*5 + t] = fc[t] - lse;
    if (t < 256 && out_size >= Bb*5 + Bb*Hh) out[Bb*5 + b*Hh + h] = ssv[h];
}

// ---------------- host ----------------
extern "C" void kernel_launch(void* const* d_in, const int* in_sizes, int n_in,
                              void* d_out, int out_size){
    const int*   idx       = (const int*)  d_in[0];
    const float* hh0       = (const float*)d_in[2];
    const float* cs0       = (const float*)d_in[3];
    const float* embed     = (const float*)d_in[4];
    const float* W_lr      = (const float*)d_in[5];
    const float* W_c       = (const float*)d_in[6];
    const float* W_x       = (const float*)d_in[7];
    const float* W_g       = (const float*)d_in[8];
    const float* gate_bias = (const float*)d_in[9];
    const float* W_fg_g    = (const float*)d_in[10];
    const float* W_fg_h    = (const float*)d_in[11];
    const float* W_fgi_g   = (const float*)d_in[12];
    const float* W_fgi_h   = (const float*)d_in[13];
    const float* W_og_g    = (const float*)d_in[14];
    const float* W_og_h    = (const float*)d_in[15];
    const float* b_fg      = (const float*)d_in[16];
    const float* b_fgi     = (const float*)d_in[17];
    const float* W1        = (const float*)d_in[18];
    const float* b1        = (const float*)d_in[19];
    const float* Wout      = (const float*)d_in[20];
    const float* bout      = (const float*)d_in[21];
    float* out = (float*)d_out;

    float* d_Wgt; cudaGetSymbolAddress((void**)&d_Wgt, g_Wgt);
    float* d_W1t; cudaGetSymbolAddress((void**)&d_W1t, g_W1t);

    cudaFuncSetAttribute(k_mma, cudaFuncAttributeMaxDynamicSharedMemorySize, SMEM_MMA);

    k_wsplit<<<NG2, 128>>>(W_lr, W_c, W_x, W_fgi_h);
    k_tpose<<<dim3(8, 56), dim3(32, 8)>>>(W_g, d_Wgt, NG, Hh);     // W_g [1792x256] -> [256x1792]
    k_wsmt<<<dim3(8, 8, 5), dim3(32, 8)>>>(W_fg_g, W_fg_h, W_og_g, W_og_h, W_fgi_g);
    k_tpose<<<dim3(16, 8), dim3(32, 8)>>>(W1, d_W1t, Hh, 512);     // W1 [256x512] -> [512x256]

    int p = 0;
    for (int layer = 0; layer < 2; layer++){
        int q = 1 - p;
        const float* hh_ext = (layer == 0) ? hh0 : nullptr;
        const float* cs_ext = (layer == 0) ? cs0 : nullptr;
        k_buildXs<<<BS/8, 1024>>>(idx, embed, hh_ext, p);
        k_small<<<Bb, 1024>>>(b_fg, gate_bias, hh_ext, cs_ext, p);
        k_mma<<<NCTA, 128, SMEM_MMA>>>(NTILE);
        k_fgi<<<BS/8, 256>>>(b_fgi, cs_ext, p);
        k_scsbias<<<dim3(7, Bb), 1024>>>(gate_bias, p, q);
        k_act<<<BS/8, 256>>>(cs_ext, p, q);
        p = q;
    }
    k_head<<<Bb, 1024>>>(b1, Wout, bout, p, out, out_size);
}